// round 11
// baseline (speedup 1.0000x reference)
#include <cuda_runtime.h>
#include <cuda_fp16.h>
#include <cuda_bf16.h>
#include <cstdint>

// ============================================================================
// VQ quantizer: single-pass fp16 mma.sync prefilter with *fp16 accumulators*
// (2x tensor rate on consumer-style fallback) + per-row rigorous error bound
// + provably-exact fp32 argmin rescue.
// z [N,64] f32, codebook [512,64] f32.
// Outputs (concatenated f32): q_ste [N*64], loss [1], ids [N] (as float).
// ============================================================================

#define D        64
#define KCODES   512
#define MTILE    128
#define TPB      256
#define GRID_MAX 296   // 2 CTAs/SM x 148 SMs

// smem layout (byte offsets); fp16 rows strided 144B => conflict-free frags
#define B_OFF      0        // 512 x 144B fp16 codebook (k-contiguous rows)
#define A_OFF      73728    // 128 x 144B fp16 z tile
#define C2H_OFF    92160    // 512 f32: 0.5*||c||^2
#define C2P_OFF    94208    // 256 u32: packed half2(-0.5*c2[2i], -0.5*c2[2i+1])
#define Z2S_OFF    95232    // 128 f32: approx ||z||^2 per tile row
#define KID_OFF    95744    // 128 int
#define CN_OFF     96256    // 1 f32: max ||c||
#define SMEM_TOTAL 96384

__device__ double g_partial[4096];

// ---------------- helpers ----------------
// fp16-accumulate MMA: D(f16) = A(f16)*B(f16) + C(f16) — 2x rate vs f32 acc
__device__ __forceinline__ void mma_fp16_acc16(uint32_t* c, const uint32_t* a,
                                               uint32_t b0, uint32_t b1) {
    asm volatile(
        "mma.sync.aligned.m16n8k16.row.col.f16.f16.f16.f16 "
        "{%0,%1}, {%2,%3,%4,%5}, {%6,%7}, {%0,%1};"
        : "+r"(c[0]), "+r"(c[1])
        : "r"(a[0]), "r"(a[1]), "r"(a[2]), "r"(a[3]), "r"(b0), "r"(b1));
}

// top-3 insert (descending)
__device__ __forceinline__ void ins3(float v, int k, float* tv, int* tk) {
    if (v > tv[2]) {
        if (v > tv[0])      { tv[2]=tv[1]; tk[2]=tk[1]; tv[1]=tv[0]; tk[1]=tk[0]; tv[0]=v; tk[0]=k; }
        else if (v > tv[1]) { tv[2]=tv[1]; tk[2]=tk[1]; tv[1]=v; tk[1]=k; }
        else                { tv[2]=v; tk[2]=k; }
    }
}

// EXACT scorer — replicates round-1 arithmetic (verified rel_err 0.0)
__device__ __forceinline__ float exact_d2(const float4* zr, float z2,
                                          const float* __restrict__ crow) {
    const float4* c4 = (const float4*)crow;
    float4 cv[16];
    #pragma unroll
    for (int i = 0; i < 16; i++) cv[i] = c4[i];
    float c2 = 0.f;
    #pragma unroll
    for (int i = 0; i < 16; i++) {
        c2 += cv[i].x * cv[i].x; c2 += cv[i].y * cv[i].y;
        c2 += cv[i].z * cv[i].z; c2 += cv[i].w * cv[i].w;
    }
    float a0 = 0.f, a1 = 0.f, a2 = 0.f, a3 = 0.f;
    #pragma unroll
    for (int i = 0; i < 16; i++) {
        a0 += zr[i].x * cv[i].x;
        a1 += zr[i].y * cv[i].y;
        a2 += zr[i].z * cv[i].z;
        a3 += zr[i].w * cv[i].w;
    }
    float dot = (a0 + a1) + (a2 + a3);
    return (z2 - 2.0f * dot) + c2;
}

__device__ __forceinline__ float z2_of(const float4* zr) {
    float z2 = 0.f;
    #pragma unroll
    for (int i = 0; i < 16; i++)
        z2 += zr[i].x * zr[i].x + zr[i].y * zr[i].y
            + zr[i].z * zr[i].z + zr[i].w * zr[i].w;
    return z2;
}

// convert 64 f32 -> fp16 row (144B stride), return sum of squares (approx ok)
__device__ __forceinline__ float stage_row_fp16(char* dst, const float4* v) {
    float s = 0.f;
    #pragma unroll
    for (int i = 0; i < 16; i++) {
        float4 a = v[i];
        s += a.x * a.x + a.y * a.y + a.z * a.z + a.w * a.w;
        __half2 h0 = __halves2half2(__float2half_rn(a.x), __float2half_rn(a.y));
        __half2 h1 = __halves2half2(__float2half_rn(a.z), __float2half_rn(a.w));
        uint2 w;
        w.x = *(uint32_t*)&h0;
        w.y = *(uint32_t*)&h1;
        *(uint2*)(dst + i * 8) = w;
    }
    return s;
}

// ============================================================================
// Main kernel: persistent, 2 CTAs/SM, 8 warps, M-tile 128 (1 m16 strip/warp)
// ============================================================================
__global__ __launch_bounds__(TPB, 2)
void vq_mma(const float* __restrict__ z, const float* __restrict__ cb,
            int N, float* __restrict__ q_out, float* __restrict__ ids_out)
{
    extern __shared__ char smem[];
    const int tid  = threadIdx.x;
    const int wid  = tid >> 5;
    const int lane = tid & 31;
    const int qr   = lane >> 2;   // 0..7
    const int qc   = lane & 3;    // 0..3

    float*    c2h  = (float*)(smem + C2H_OFF);
    uint32_t* c2p  = (uint32_t*)(smem + C2P_OFF);
    float*    z2s  = (float*)(smem + Z2S_OFF);
    int*      kidS = (int*)(smem + KID_OFF);
    float*    cnp  = (float*)(smem + CN_OFF);

    // ---- stage codebook once: fp16 rows + 0.5*||c||^2 ----
    for (int n = tid; n < KCODES; n += TPB) {
        float4 cv[16];
        const float4* c4 = (const float4*)(cb + (size_t)n * D);
        #pragma unroll
        for (int i = 0; i < 16; i++) cv[i] = c4[i];
        float s = stage_row_fp16(smem + B_OFF + n * 144, cv);
        c2h[n] = 0.5f * s;
    }
    __syncthreads();
    // packed -0.5*||c||^2 per code pair (fp16 accumulator init values)
    if (tid < KCODES / 2) {
        __half2 p = __halves2half2(__float2half_rn(-c2h[2 * tid]),
                                   __float2half_rn(-c2h[2 * tid + 1]));
        c2p[tid] = *(uint32_t*)&p;
    }
    if (tid < 32) {
        float m = 0.f;
        for (int i = tid; i < KCODES; i += 32) m = fmaxf(m, c2h[i]);
        #pragma unroll
        for (int off = 16; off; off >>= 1)
            m = fmaxf(m, __shfl_xor_sync(0xffffffffu, m, off));
        if (tid == 0) *cnp = sqrtf(2.0f * m);
    }
    __syncthreads();
    const float CNMAX = *cnp;

    const int ntiles = N / MTILE;
    double dsum = 0.0;

    for (int tile = blockIdx.x; tile < ntiles; tile += gridDim.x) {
        // ---- stage A tile: threads 0..127 convert one row each ----
        if (tid < MTILE) {
            float4 zr[16];
            const float4* zp = (const float4*)(z + (size_t)(tile * MTILE + tid) * D);
            #pragma unroll
            for (int i = 0; i < 16; i++) zr[i] = zp[i];
            z2s[tid] = stage_row_fp16(smem + A_OFF + tid * 144, zr);
        }
        __syncthreads();

        // ---- A fragments (hoisted; strip rows wid*16+qr, +8) ----
        uint32_t afr[4][4];
        {
            const int r0b = (wid * 16 + qr) * 144;
            #pragma unroll
            for (int ks = 0; ks < 4; ks++) {
                const int kb = ks * 32 + qc * 4;
                afr[ks][0] = *(const uint32_t*)(smem + A_OFF + r0b + kb);
                afr[ks][1] = *(const uint32_t*)(smem + A_OFF + r0b + 8 * 144 + kb);
                afr[ks][2] = *(const uint32_t*)(smem + A_OFF + r0b + kb + 16);
                afr[ks][3] = *(const uint32_t*)(smem + A_OFF + r0b + 8 * 144 + kb + 16);
            }
        }

        // ---- MMA (fp16 acc) + per-thread top-3 for 2 row-slots ----
        float tv[2][3];
        int   tk[2][3];
        #pragma unroll
        for (int s = 0; s < 2; s++) {
            tv[s][0] = tv[s][1] = tv[s][2] = -3.4e38f;
            tk[s][0] = tk[s][1] = tk[s][2] = 0;
        }

        for (int ch = 0; ch < 8; ch++) {       // 8 chunks of 64 codes
            uint32_t acc[8][2];
            #pragma unroll
            for (int n8 = 0; n8 < 8; n8++) {   // init acc = -0.5*||c||^2 (packed)
                const uint32_t p = c2p[ch * 32 + n8 * 4 + qc];
                acc[n8][0] = p;                // rows qr   (cols 2qc, 2qc+1)
                acc[n8][1] = p;                // rows qr+8
            }
            #pragma unroll
            for (int ks = 0; ks < 4; ks++) {
                const int kb = ks * 32 + qc * 4;
                #pragma unroll
                for (int n8 = 0; n8 < 8; n8++) {
                    const int cbyte = (ch * 64 + n8 * 8 + qr) * 144 + kb;
                    uint32_t b0 = *(const uint32_t*)(smem + B_OFF + cbyte);
                    uint32_t b1 = *(const uint32_t*)(smem + B_OFF + cbyte + 16);
                    mma_fp16_acc16(acc[n8], afr[ks], b0, b1);
                }
            }
            #pragma unroll
            for (int n8 = 0; n8 < 8; n8++) {
                const int col0 = ch * 64 + n8 * 8 + qc * 2;
                float2 v0 = __half22float2(*(__half2*)&acc[n8][0]);
                float2 v1 = __half22float2(*(__half2*)&acc[n8][1]);
                ins3(v0.x, col0,     tv[0], tk[0]);
                ins3(v0.y, col0 + 1, tv[0], tk[0]);
                ins3(v1.x, col0,     tv[1], tk[1]);
                ins3(v1.y, col0 + 1, tv[1], tk[1]);
            }
        }

        const float loc3_0 = tv[0][2];
        const float loc3_1 = tv[1][2];

        // ---- quad merge (xor 1, 2) -> global top-3 per slot ----
        #pragma unroll
        for (int off = 1; off <= 2; off <<= 1) {
            #pragma unroll
            for (int s = 0; s < 2; s++) {
                float sv0 = tv[s][0], sv1 = tv[s][1], sv2 = tv[s][2];
                int   sk0 = tk[s][0], sk1 = tk[s][1], sk2 = tk[s][2];
                float ov0 = __shfl_xor_sync(0xffffffffu, sv0, off);
                float ov1 = __shfl_xor_sync(0xffffffffu, sv1, off);
                float ov2 = __shfl_xor_sync(0xffffffffu, sv2, off);
                int   ok0 = __shfl_xor_sync(0xffffffffu, sk0, off);
                int   ok1 = __shfl_xor_sync(0xffffffffu, sk1, off);
                int   ok2 = __shfl_xor_sync(0xffffffffu, sk2, off);
                ins3(ov0, ok0, tv[s], tk[s]);
                ins3(ov1, ok1, tv[s], tk[s]);
                ins3(ov2, ok2, tv[s], tk[s]);
            }
        }

        // ---- per-row rigorous threshold ----
        // input rounding (2^-9 w/ slack) + fp16 accumulation: 5 roundings at
        // 2^-11 of magnitude <= ||z||*CN + CN^2/2
        const int r0 = wid * 16 + qr;
        const float zn0 = sqrtf(z2s[r0]);
        const float zn1 = sqrtf(z2s[r0 + 8]);
        const float cterm = CNMAX * CNMAX * 0.0013f + 5e-4f;
        const float thr0 = zn0 * CNMAX * 0.0045f + cterm;
        const float thr1 = zn1 * CNMAX * 0.0045f + cterm;

        unsigned bal0 = __ballot_sync(0xffffffffu, loc3_0 >= tv[0][0] - thr0);
        unsigned bal1 = __ballot_sync(0xffffffffu, loc3_1 >= tv[1][0] - thr1);
        const unsigned qsh = lane & ~3;
        const bool u0 = ((bal0 >> qsh) & 0xFu) != 0;
        const bool u1 = ((bal1 >> qsh) & 0xFu) != 0;

        // ---- finalize: lane qc=0 -> slot 0, qc=1 -> slot 1 ----
        const bool mine = (qc < 2);
        const int  myrow = r0 + qc * 8;                 // valid when mine
        const bool my_unsafe = mine && (qc == 0 ? u0 : u1);
        int kid = 0;

        if (mine && !my_unsafe) {
            float b0v, b1v, b2v, myTHR;
            int   k0v, k1v, k2v;
            if (qc == 0) { b0v=tv[0][0]; b1v=tv[0][1]; b2v=tv[0][2];
                           k0v=tk[0][0]; k1v=tk[0][1]; k2v=tk[0][2]; myTHR=thr0; }
            else         { b0v=tv[1][0]; b1v=tv[1][1]; b2v=tv[1][2];
                           k0v=tk[1][0]; k1v=tk[1][1]; k2v=tk[1][2]; myTHR=thr1; }
            const float thrv = b0v - myTHR;
            int ck[3]; int nc = 1;
            ck[0] = k0v;
            if (b1v >= thrv) ck[nc++] = k1v;
            if (b2v >= thrv) ck[nc++] = k2v;
            if (nc == 1) {
                kid = ck[0];                            // margin proves winner
            } else {
                if (ck[0] > ck[1]) { int t = ck[0]; ck[0] = ck[1]; ck[1] = t; }
                if (nc == 3) {
                    if (ck[1] > ck[2]) { int t = ck[1]; ck[1] = ck[2]; ck[2] = t; }
                    if (ck[0] > ck[1]) { int t = ck[0]; ck[0] = ck[1]; ck[1] = t; }
                }
                const int grow = tile * MTILE + myrow;
                float4 zr[16];
                const float4* zp = (const float4*)(z + (size_t)grow * D);
                #pragma unroll
                for (int i = 0; i < 16; i++) zr[i] = zp[i];
                const float z2 = z2_of(zr);
                float best = 3.402823466e38f; kid = ck[0];
                for (int i = 0; i < nc; i++) {          // ascending k, strict <
                    float d = exact_d2(zr, z2, cb + (size_t)ck[i] * D);
                    if (d < best) { best = d; kid = ck[i]; }
                }
            }
        }

        // ---- warp-cooperative exact scan for unsafe rows (rare) ----
        unsigned need = __ballot_sync(0xffffffffu, my_unsafe);
        while (need) {
            const int src = __ffs(need) - 1;
            need &= need - 1;
            const int rl = __shfl_sync(0xffffffffu, myrow, src);
            const int grow = tile * MTILE + rl;
            float4 zr[16];
            const float4* zp = (const float4*)(z + (size_t)grow * D);
            #pragma unroll
            for (int i = 0; i < 16; i++) zr[i] = zp[i];
            const float z2 = z2_of(zr);
            float best = 3.402823466e38f; int bk = KCODES;
            for (int k = lane; k < KCODES; k += 32) {   // lane-ascending, strict <
                float d = exact_d2(zr, z2, cb + (size_t)k * D);
                if (d < best) { best = d; bk = k; }
            }
            #pragma unroll
            for (int off = 16; off; off >>= 1) {
                float ob = __shfl_xor_sync(0xffffffffu, best, off);
                int   obk = __shfl_xor_sync(0xffffffffu, bk, off);
                if (ob < best || (ob == best && obk < bk)) { best = ob; bk = obk; }
            }
            if (lane == src) kid = bk;
        }

        if (mine) kidS[myrow] = kid;
        __syncthreads();

        // ---- epilogue: threads 0..127, row tid ----
        if (tid < MTILE) {
            const int grow = tile * MTILE + tid;
            const int k = kidS[tid];
            float4 zr[16];
            const float4* zp = (const float4*)(z + (size_t)grow * D);
            #pragma unroll
            for (int i = 0; i < 16; i++) zr[i] = zp[i];
            const float4* q4 = (const float4*)(cb + (size_t)k * D);
            float4* qo = (float4*)(q_out + (size_t)grow * D);
            float lsum = 0.f;
            #pragma unroll
            for (int i = 0; i < 16; i++) {
                float4 cv = q4[i];
                float4 zv = zr[i];
                float dx = zv.x - cv.x, dy = zv.y - cv.y;
                float dz = zv.z - cv.z, dw = zv.w - cv.w;
                lsum += dx * dx + dy * dy + dz * dz + dw * dw;
                float4 o;
                o.x = zv.x + (cv.x - zv.x);   // fl(z + fl(q - z)), reference STE
                o.y = zv.y + (cv.y - zv.y);
                o.z = zv.z + (cv.z - zv.z);
                o.w = zv.w + (cv.w - zv.w);
                qo[i] = o;
            }
            if (ids_out) ids_out[grow] = (float)k;
            dsum += (double)lsum;
        }
        __syncthreads();
    }

    // ---- deterministic per-CTA loss reduction ----
    double* red = (double*)(smem + B_OFF);   // codebook region reusable now
    red[tid] = dsum;
    __syncthreads();
    if (tid == 0) {
        double s = 0.0;
        for (int i = 0; i < TPB; i++) s += red[i];
        g_partial[blockIdx.x] = s;
    }
}

// ============================================================================
// Generic fallback (round-2 kernel) for unexpected shapes
// ============================================================================
#define FTPB 256
#define ROW_PAD 68
__global__ __launch_bounds__(FTPB) void vq_ref(
    const float* __restrict__ z, const float* __restrict__ cb,
    int N, int K, float* __restrict__ q_out, float* __restrict__ ids_out)
{
    extern __shared__ float fsm[];
    float* cbs = fsm;
    float* c2  = fsm + (size_t)K * ROW_PAD;
    const int tid = threadIdx.x;
    const float4* cb4 = (const float4*)cb;
    const int nvec = K * (D / 4);
    for (int idx = tid; idx < nvec; idx += FTPB) {
        int k = idx >> 4, c = idx & 15;
        *(float4*)&cbs[k * ROW_PAD + c * 4] = cb4[idx];
    }
    __syncthreads();
    for (int k = tid; k < K; k += FTPB) {
        const float* r = &cbs[k * ROW_PAD];
        float s = 0.f;
        #pragma unroll
        for (int i = 0; i < D; i++) s += r[i] * r[i];
        c2[k] = s;
    }
    __syncthreads();
    const int row = blockIdx.x * FTPB + tid;
    float lsum = 0.f;
    if (row < N) {
        float4 zr[16];
        const float4* zp = (const float4*)(z + (size_t)row * D);
        #pragma unroll
        for (int i = 0; i < 16; i++) zr[i] = zp[i];
        float z2 = 0.f;
        #pragma unroll
        for (int i = 0; i < 16; i++)
            z2 += zr[i].x * zr[i].x + zr[i].y * zr[i].y
                + zr[i].z * zr[i].z + zr[i].w * zr[i].w;
        float best = 3.402823466e38f; int bid = 0;
        for (int k = 0; k < K; k++) {
            const float4* crow = (const float4*)&cbs[k * ROW_PAD];
            float a0 = 0.f, a1 = 0.f, a2 = 0.f, a3 = 0.f;
            #pragma unroll
            for (int i = 0; i < 16; i++) {
                float4 cv = crow[i];
                a0 += zr[i].x * cv.x; a1 += zr[i].y * cv.y;
                a2 += zr[i].z * cv.z; a3 += zr[i].w * cv.w;
            }
            float dot = (a0 + a1) + (a2 + a3);
            float d = (z2 - 2.0f * dot) + c2[k];
            if (d < best) { best = d; bid = k; }
        }
        const float4* crow = (const float4*)&cbs[bid * ROW_PAD];
        float4* qo = (float4*)(q_out + (size_t)row * D);
        #pragma unroll
        for (int i = 0; i < 16; i++) {
            float4 cv = crow[i];
            float4 zv = zr[i];
            float dx = zv.x - cv.x, dy = zv.y - cv.y;
            float dz = zv.z - cv.z, dw = zv.w - cv.w;
            lsum += dx * dx + dy * dy + dz * dz + dw * dw;
            float4 o;
            o.x = zv.x + (cv.x - zv.x); o.y = zv.y + (cv.y - zv.y);
            o.z = zv.z + (cv.z - zv.z); o.w = zv.w + (cv.w - zv.w);
            qo[i] = o;
        }
        if (ids_out) ids_out[row] = (float)bid;
    }
    #pragma unroll
    for (int off = 16; off; off >>= 1)
        lsum += __shfl_down_sync(0xffffffffu, lsum, off);
    __shared__ double wp[FTPB / 32];
    if ((tid & 31) == 0) wp[tid >> 5] = (double)lsum;
    __syncthreads();
    if (tid == 0) {
        double s = 0.0;
        #pragma unroll
        for (int w = 0; w < FTPB / 32; w++) s += wp[w];
        g_partial[blockIdx.x] = s;
    }
}

__global__ void vq_finalize(int nblocks, double inv_total, float* loss_out)
{
    __shared__ double sp[256];
    const int tid = threadIdx.x;
    double s = 0.0;
    for (int i = tid; i < nblocks; i += 256) s += g_partial[i];
    sp[tid] = s;
    __syncthreads();
    for (int off = 128; off; off >>= 1) {
        if (tid < off) sp[tid] += sp[tid + off];
        __syncthreads();
    }
    if (tid == 0) {
        double mean = sp[0] * inv_total;
        loss_out[0] = (float)(mean + 0.25 * mean);
    }
}

extern "C" void kernel_launch(void* const* d_in, const int* in_sizes, int n_in,
                              void* d_out, int out_size)
{
    const float* z  = (const float*)d_in[0];
    const float* cb = (const float*)d_in[1];
    const int N = in_sizes[0] / D;
    const int K = in_sizes[1] / D;

    float* out = (float*)d_out;
    float* q_out    = out;
    float* loss_ptr = nullptr;
    float* ids_ptr  = nullptr;
    const long base = (long)N * D;
    if ((long)out_size >= base + 1 + N) { loss_ptr = out + base; ids_ptr = out + base + 1; }
    else if ((long)out_size == base + N) { ids_ptr = out + base; }
    else if ((long)out_size == base + 1) { loss_ptr = out + base; }

    int nblocks;
    if (K == KCODES && (N % MTILE) == 0 && N > 0) {
        const int ntiles = N / MTILE;
        nblocks = ntiles < GRID_MAX ? ntiles : GRID_MAX;
        cudaFuncSetAttribute(vq_mma, cudaFuncAttributeMaxDynamicSharedMemorySize, SMEM_TOTAL);
        vq_mma<<<nblocks, TPB, SMEM_TOTAL>>>(z, cb, N, q_out, ids_ptr);
    } else {
        const size_t smem_bytes = ((size_t)K * ROW_PAD + K) * sizeof(float);
        cudaFuncSetAttribute(vq_ref, cudaFuncAttributeMaxDynamicSharedMemorySize, (int)smem_bytes);
        nblocks = (N + FTPB - 1) / FTPB;
        vq_ref<<<nblocks, FTPB, smem_bytes>>>(z, cb, N, K, q_out, ids_ptr);
    }

    if (loss_ptr) {
        double inv_total = 1.0 / ((double)N * (double)D);
        vq_finalize<<<1, 256>>>(nblocks, inv_total, loss_ptr);
    }
}

// round 12
// speedup vs baseline: 1.0361x; 1.0361x over previous
#include <cuda_runtime.h>
#include <cuda_fp16.h>
#include <cuda_bf16.h>
#include <cstdint>

// ============================================================================
// VQ quantizer: single-pass fp16 mma.sync prefilter (f32 accumulators,
// per-row rigorous error bound) + provably-exact fp32 argmin rescue.
// R11 = R6 structure + full-width staging + pair-max score-scan pruning.
// z [N,64] f32, codebook [512,64] f32.
// Outputs (concatenated f32): q_ste [N*64], loss [1], ids [N] (as float).
// ============================================================================

#define D        64
#define KCODES   512
#define MTILE    128
#define TPB      256
#define GRID_MAX 296   // 2 CTAs/SM x 148 SMs

// smem layout (byte offsets); fp16 rows strided 144B => conflict-free frags
#define B_OFF      0        // 512 x 144B fp16 codebook (k-contiguous rows)
#define A_OFF      73728    // 128 x 144B fp16 z tile
#define C2H_OFF    92160    // 512 f32: 0.5*||c||^2
#define Z2S_OFF    94208    // 128 f32: approx ||z||^2 per tile row
#define KID_OFF    94720    // 128 int
#define CN_OFF     95232    // 1 f32: max ||c||
#define SMEM_TOTAL 95744

__device__ double g_partial[4096];

// ---------------- helpers ----------------
__device__ __forceinline__ void mma_fp16(float* c, const uint32_t* a,
                                         uint32_t b0, uint32_t b1) {
    asm volatile(
        "mma.sync.aligned.m16n8k16.row.col.f32.f16.f16.f32 "
        "{%0,%1,%2,%3}, {%4,%5,%6,%7}, {%8,%9}, {%0,%1,%2,%3};"
        : "+f"(c[0]), "+f"(c[1]), "+f"(c[2]), "+f"(c[3])
        : "r"(a[0]), "r"(a[1]), "r"(a[2]), "r"(a[3]), "r"(b0), "r"(b1));
}

// top-3 insert (descending)
__device__ __forceinline__ void ins3(float v, int k, float* tv, int* tk) {
    if (v > tv[2]) {
        if (v > tv[0])      { tv[2]=tv[1]; tk[2]=tk[1]; tv[1]=tv[0]; tk[1]=tk[0]; tv[0]=v; tk[0]=k; }
        else if (v > tv[1]) { tv[2]=tv[1]; tk[2]=tk[1]; tv[1]=v; tk[1]=k; }
        else                { tv[2]=v; tk[2]=k; }
    }
}

// EXACT scorer — replicates round-1 arithmetic (verified rel_err 0.0)
__device__ __forceinline__ float exact_d2(const float4* zr, float z2,
                                          const float* __restrict__ crow) {
    const float4* c4 = (const float4*)crow;
    float4 cv[16];
    #pragma unroll
    for (int i = 0; i < 16; i++) cv[i] = c4[i];
    float c2 = 0.f;
    #pragma unroll
    for (int i = 0; i < 16; i++) {
        c2 += cv[i].x * cv[i].x; c2 += cv[i].y * cv[i].y;
        c2 += cv[i].z * cv[i].z; c2 += cv[i].w * cv[i].w;
    }
    float a0 = 0.f, a1 = 0.f, a2 = 0.f, a3 = 0.f;
    #pragma unroll
    for (int i = 0; i < 16; i++) {
        a0 += zr[i].x * cv[i].x;
        a1 += zr[i].y * cv[i].y;
        a2 += zr[i].z * cv[i].z;
        a3 += zr[i].w * cv[i].w;
    }
    float dot = (a0 + a1) + (a2 + a3);
    return (z2 - 2.0f * dot) + c2;
}

__device__ __forceinline__ float z2_of(const float4* zr) {
    float z2 = 0.f;
    #pragma unroll
    for (int i = 0; i < 16; i++)
        z2 += zr[i].x * zr[i].x + zr[i].y * zr[i].y
            + zr[i].z * zr[i].z + zr[i].w * zr[i].w;
    return z2;
}

// convert 64 f32 -> fp16 row (144B stride), return sum of squares (approx ok)
__device__ __forceinline__ float stage_row_fp16(char* dst, const float4* v) {
    float s = 0.f;
    #pragma unroll
    for (int i = 0; i < 16; i++) {
        float4 a = v[i];
        s += a.x * a.x + a.y * a.y + a.z * a.z + a.w * a.w;
        __half2 h0 = __halves2half2(__float2half_rn(a.x), __float2half_rn(a.y));
        __half2 h1 = __halves2half2(__float2half_rn(a.z), __float2half_rn(a.w));
        uint2 w;
        w.x = *(uint32_t*)&h0;
        w.y = *(uint32_t*)&h1;
        *(uint2*)(dst + i * 8) = w;
    }
    return s;
}

// ============================================================================
// Main kernel: persistent, 2 CTAs/SM, 8 warps, M-tile 128 (1 m16 strip/warp)
// ============================================================================
__global__ __launch_bounds__(TPB, 2)
void vq_mma(const float* __restrict__ z, const float* __restrict__ cb,
            int N, float* __restrict__ q_out, float* __restrict__ ids_out)
{
    extern __shared__ char smem[];
    const int tid  = threadIdx.x;
    const int wid  = tid >> 5;
    const int lane = tid & 31;
    const int qr   = lane >> 2;   // 0..7
    const int qc   = lane & 3;    // 0..3

    float* c2h  = (float*)(smem + C2H_OFF);
    float* z2s  = (float*)(smem + Z2S_OFF);
    int*   kidS = (int*)(smem + KID_OFF);
    float* cnp  = (float*)(smem + CN_OFF);

    // ---- stage codebook once: fp16 rows + 0.5*||c||^2 ----
    for (int n = tid; n < KCODES; n += TPB) {
        float4 cv[16];
        const float4* c4 = (const float4*)(cb + (size_t)n * D);
        #pragma unroll
        for (int i = 0; i < 16; i++) cv[i] = c4[i];
        float s = stage_row_fp16(smem + B_OFF + n * 144, cv);
        c2h[n] = 0.5f * s;
    }
    __syncthreads();
    if (tid < 32) {
        float m = 0.f;
        for (int i = tid; i < KCODES; i += 32) m = fmaxf(m, c2h[i]);
        #pragma unroll
        for (int off = 16; off; off >>= 1)
            m = fmaxf(m, __shfl_xor_sync(0xffffffffu, m, off));
        if (tid == 0) *cnp = sqrtf(2.0f * m);
    }
    __syncthreads();
    const float CNMAX = *cnp;

    const int ntiles = N / MTILE;
    double dsum = 0.0;

    for (int tile = blockIdx.x; tile < ntiles; tile += gridDim.x) {
        // ---- stage A tile: all 256 threads, half a row (32 floats) each ----
        {
            const int row  = tid >> 1;          // 0..127
            const int half = tid & 1;           // 0 or 1
            float4 zh[8];
            const float4* zp = (const float4*)
                (z + (size_t)(tile * MTILE + row) * D + half * 32);
            #pragma unroll
            for (int i = 0; i < 8; i++) zh[i] = zp[i];
            float s = 0.f;
            char* dst = smem + A_OFF + row * 144 + half * 64;
            #pragma unroll
            for (int i = 0; i < 8; i++) {
                float4 a = zh[i];
                s += a.x * a.x + a.y * a.y + a.z * a.z + a.w * a.w;
                __half2 h0 = __halves2half2(__float2half_rn(a.x), __float2half_rn(a.y));
                __half2 h1 = __halves2half2(__float2half_rn(a.z), __float2half_rn(a.w));
                uint2 w;
                w.x = *(uint32_t*)&h0;
                w.y = *(uint32_t*)&h1;
                *(uint2*)(dst + i * 8) = w;
            }
            // combine halves (lanes tid and tid^1 are in the same warp)
            float s2 = s + __shfl_xor_sync(0xffffffffu, s, 1);
            if (half == 0) z2s[row] = s2;
        }
        __syncthreads();

        // ---- A fragments (hoisted; strip rows wid*16+qr, +8) ----
        uint32_t afr[4][4];
        {
            const int r0b = (wid * 16 + qr) * 144;
            #pragma unroll
            for (int ks = 0; ks < 4; ks++) {
                const int kb = ks * 32 + qc * 4;
                afr[ks][0] = *(const uint32_t*)(smem + A_OFF + r0b + kb);
                afr[ks][1] = *(const uint32_t*)(smem + A_OFF + r0b + 8 * 144 + kb);
                afr[ks][2] = *(const uint32_t*)(smem + A_OFF + r0b + kb + 16);
                afr[ks][3] = *(const uint32_t*)(smem + A_OFF + r0b + 8 * 144 + kb + 16);
            }
        }

        // ---- MMA + per-thread top-3 for 2 row-slots ----
        float tv[2][3];
        int   tk[2][3];
        #pragma unroll
        for (int s = 0; s < 2; s++) {
            tv[s][0] = tv[s][1] = tv[s][2] = -3.4e38f;
            tk[s][0] = tk[s][1] = tk[s][2] = 0;
        }

        for (int ch = 0; ch < 8; ch++) {       // 8 chunks of 64 codes
            float acc[8][4];
            #pragma unroll
            for (int n8 = 0; n8 < 8; n8++) {   // init acc = -0.5*||c||^2
                const int col0 = ch * 64 + n8 * 8 + qc * 2;
                const float h0 = c2h[col0], h1 = c2h[col0 + 1];
                acc[n8][0] = -h0; acc[n8][1] = -h1;
                acc[n8][2] = -h0; acc[n8][3] = -h1;
            }
            #pragma unroll
            for (int ks = 0; ks < 4; ks++) {
                const int kb = ks * 32 + qc * 4;
                #pragma unroll
                for (int n8 = 0; n8 < 8; n8++) {
                    const int cbyte = (ch * 64 + n8 * 8 + qr) * 144 + kb;
                    uint32_t b0 = *(const uint32_t*)(smem + B_OFF + cbyte);
                    uint32_t b1 = *(const uint32_t*)(smem + B_OFF + cbyte + 16);
                    mma_fp16(acc[n8], afr[ks], b0, b1);
                }
            }
            // pair-max pruned scan
            #pragma unroll
            for (int n8 = 0; n8 < 8; n8++) {
                const int col0 = ch * 64 + n8 * 8 + qc * 2;
                if (fmaxf(acc[n8][0], acc[n8][1]) > tv[0][2]) {
                    ins3(acc[n8][0], col0,     tv[0], tk[0]);
                    ins3(acc[n8][1], col0 + 1, tv[0], tk[0]);
                }
                if (fmaxf(acc[n8][2], acc[n8][3]) > tv[1][2]) {
                    ins3(acc[n8][2], col0,     tv[1], tk[1]);
                    ins3(acc[n8][3], col0 + 1, tv[1], tk[1]);
                }
            }
        }

        const float loc3_0 = tv[0][2];
        const float loc3_1 = tv[1][2];

        // ---- quad merge (xor 1, 2) -> global top-3 per slot ----
        #pragma unroll
        for (int off = 1; off <= 2; off <<= 1) {
            #pragma unroll
            for (int s = 0; s < 2; s++) {
                float sv0 = tv[s][0], sv1 = tv[s][1], sv2 = tv[s][2];
                int   sk0 = tk[s][0], sk1 = tk[s][1], sk2 = tk[s][2];
                float ov0 = __shfl_xor_sync(0xffffffffu, sv0, off);
                float ov1 = __shfl_xor_sync(0xffffffffu, sv1, off);
                float ov2 = __shfl_xor_sync(0xffffffffu, sv2, off);
                int   ok0 = __shfl_xor_sync(0xffffffffu, sk0, off);
                int   ok1 = __shfl_xor_sync(0xffffffffu, sk1, off);
                int   ok2 = __shfl_xor_sync(0xffffffffu, sk2, off);
                ins3(ov0, ok0, tv[s], tk[s]);
                ins3(ov1, ok1, tv[s], tk[s]);
                ins3(ov2, ok2, tv[s], tk[s]);
            }
        }

        // ---- per-row rigorous threshold: 2e <= 2^-9 * ||z|| * ||c||max ----
        const int r0 = wid * 16 + qr;
        const float thr0 = sqrtf(z2s[r0])     * CNMAX * 0.001953125f + 5e-4f;
        const float thr1 = sqrtf(z2s[r0 + 8]) * CNMAX * 0.001953125f + 5e-4f;

        unsigned bal0 = __ballot_sync(0xffffffffu, loc3_0 >= tv[0][0] - thr0);
        unsigned bal1 = __ballot_sync(0xffffffffu, loc3_1 >= tv[1][0] - thr1);
        const unsigned qsh = lane & ~3;
        const bool u0 = ((bal0 >> qsh) & 0xFu) != 0;
        const bool u1 = ((bal1 >> qsh) & 0xFu) != 0;

        // ---- finalize: lane qc=0 -> slot 0, qc=1 -> slot 1 ----
        const bool mine = (qc < 2);
        const int  myrow = r0 + qc * 8;                 // valid when mine
        const bool my_unsafe = mine && (qc == 0 ? u0 : u1);
        int kid = 0;

        if (mine && !my_unsafe) {
            float b0v, b1v, b2v, myTHR;
            int   k0v, k1v, k2v;
            if (qc == 0) { b0v=tv[0][0]; b1v=tv[0][1]; b2v=tv[0][2];
                           k0v=tk[0][0]; k1v=tk[0][1]; k2v=tk[0][2]; myTHR=thr0; }
            else         { b0v=tv[1][0]; b1v=tv[1][1]; b2v=tv[1][2];
                           k0v=tk[1][0]; k1v=tk[1][1]; k2v=tk[1][2]; myTHR=thr1; }
            const float thrv = b0v - myTHR;
            int ck[3]; int nc = 1;
            ck[0] = k0v;
            if (b1v >= thrv) ck[nc++] = k1v;
            if (b2v >= thrv) ck[nc++] = k2v;
            if (nc == 1) {
                kid = ck[0];                            // margin proves winner
            } else {
                if (ck[0] > ck[1]) { int t = ck[0]; ck[0] = ck[1]; ck[1] = t; }
                if (nc == 3) {
                    if (ck[1] > ck[2]) { int t = ck[1]; ck[1] = ck[2]; ck[2] = t; }
                    if (ck[0] > ck[1]) { int t = ck[0]; ck[0] = ck[1]; ck[1] = t; }
                }
                const int grow = tile * MTILE + myrow;
                float4 zr[16];
                const float4* zp = (const float4*)(z + (size_t)grow * D);
                #pragma unroll
                for (int i = 0; i < 16; i++) zr[i] = zp[i];
                const float z2 = z2_of(zr);
                float best = 3.402823466e38f; kid = ck[0];
                for (int i = 0; i < nc; i++) {          // ascending k, strict <
                    float d = exact_d2(zr, z2, cb + (size_t)ck[i] * D);
                    if (d < best) { best = d; kid = ck[i]; }
                }
            }
        }

        // ---- warp-cooperative exact scan for unsafe rows (rare) ----
        unsigned need = __ballot_sync(0xffffffffu, my_unsafe);
        while (need) {
            const int src = __ffs(need) - 1;
            need &= need - 1;
            const int rl = __shfl_sync(0xffffffffu, myrow, src);
            const int grow = tile * MTILE + rl;
            float4 zr[16];
            const float4* zp = (const float4*)(z + (size_t)grow * D);
            #pragma unroll
            for (int i = 0; i < 16; i++) zr[i] = zp[i];
            const float z2 = z2_of(zr);
            float best = 3.402823466e38f; int bk = KCODES;
            for (int k = lane; k < KCODES; k += 32) {   // lane-ascending, strict <
                float d = exact_d2(zr, z2, cb + (size_t)k * D);
                if (d < best) { best = d; bk = k; }
            }
            #pragma unroll
            for (int off = 16; off; off >>= 1) {
                float ob = __shfl_xor_sync(0xffffffffu, best, off);
                int   obk = __shfl_xor_sync(0xffffffffu, bk, off);
                if (ob < best || (ob == best && obk < bk)) { best = ob; bk = obk; }
            }
            if (lane == src) kid = bk;
        }

        if (mine) kidS[myrow] = kid;
        __syncthreads();

        // ---- epilogue: threads 0..127, row tid ----
        if (tid < MTILE) {
            const int grow = tile * MTILE + tid;
            const int k = kidS[tid];
            float4 zr[16];
            const float4* zp = (const float4*)(z + (size_t)grow * D);
            #pragma unroll
            for (int i = 0; i < 16; i++) zr[i] = zp[i];
            const float4* q4 = (const float4*)(cb + (size_t)k * D);
            float4* qo = (float4*)(q_out + (size_t)grow * D);
            float lsum = 0.f;
            #pragma unroll
            for (int i = 0; i < 16; i++) {
                float4 cv = q4[i];
                float4 zv = zr[i];
                float dx = zv.x - cv.x, dy = zv.y - cv.y;
                float dz = zv.z - cv.z, dw = zv.w - cv.w;
                lsum += dx * dx + dy * dy + dz * dz + dw * dw;
                float4 o;
                o.x = zv.x + (cv.x - zv.x);   // fl(z + fl(q - z)), reference STE
                o.y = zv.y + (cv.y - zv.y);
                o.z = zv.z + (cv.z - zv.z);
                o.w = zv.w + (cv.w - zv.w);
                qo[i] = o;
            }
            if (ids_out) ids_out[grow] = (float)k;
            dsum += (double)lsum;
        }
        __syncthreads();
    }

    // ---- deterministic per-CTA loss reduction ----
    double* red = (double*)(smem + B_OFF);   // codebook region reusable now
    red[tid] = dsum;
    __syncthreads();
    if (tid == 0) {
        double s = 0.0;
        for (int i = 0; i < TPB; i++) s += red[i];
        g_partial[blockIdx.x] = s;
    }
}

// ============================================================================
// Generic fallback (round-2 kernel) for unexpected shapes
// ============================================================================
#define FTPB 256
#define ROW_PAD 68
__global__ __launch_bounds__(FTPB) void vq_ref(
    const float* __restrict__ z, const float* __restrict__ cb,
    int N, int K, float* __restrict__ q_out, float* __restrict__ ids_out)
{
    extern __shared__ float fsm[];
    float* cbs = fsm;
    float* c2  = fsm + (size_t)K * ROW_PAD;
    const int tid = threadIdx.x;
    const float4* cb4 = (const float4*)cb;
    const int nvec = K * (D / 4);
    for (int idx = tid; idx < nvec; idx += FTPB) {
        int k = idx >> 4, c = idx & 15;
        *(float4*)&cbs[k * ROW_PAD + c * 4] = cb4[idx];
    }
    __syncthreads();
    for (int k = tid; k < K; k += FTPB) {
        const float* r = &cbs[k * ROW_PAD];
        float s = 0.f;
        #pragma unroll
        for (int i = 0; i < D; i++) s += r[i] * r[i];
        c2[k] = s;
    }
    __syncthreads();
    const int row = blockIdx.x * FTPB + tid;
    float lsum = 0.f;
    if (row < N) {
        float4 zr[16];
        const float4* zp = (const float4*)(z + (size_t)row * D);
        #pragma unroll
        for (int i = 0; i < 16; i++) zr[i] = zp[i];
        float z2 = 0.f;
        #pragma unroll
        for (int i = 0; i < 16; i++)
            z2 += zr[i].x * zr[i].x + zr[i].y * zr[i].y
                + zr[i].z * zr[i].z + zr[i].w * zr[i].w;
        float best = 3.402823466e38f; int bid = 0;
        for (int k = 0; k < K; k++) {
            const float4* crow = (const float4*)&cbs[k * ROW_PAD];
            float a0 = 0.f, a1 = 0.f, a2 = 0.f, a3 = 0.f;
            #pragma unroll
            for (int i = 0; i < 16; i++) {
                float4 cv = crow[i];
                a0 += zr[i].x * cv.x; a1 += zr[i].y * cv.y;
                a2 += zr[i].z * cv.z; a3 += zr[i].w * cv.w;
            }
            float dot = (a0 + a1) + (a2 + a3);
            float d = (z2 - 2.0f * dot) + c2[k];
            if (d < best) { best = d; bid = k; }
        }
        const float4* crow = (const float4*)&cbs[bid * ROW_PAD];
        float4* qo = (float4*)(q_out + (size_t)row * D);
        #pragma unroll
        for (int i = 0; i < 16; i++) {
            float4 cv = crow[i];
            float4 zv = zr[i];
            float dx = zv.x - cv.x, dy = zv.y - cv.y;
            float dz = zv.z - cv.z, dw = zv.w - cv.w;
            lsum += dx * dx + dy * dy + dz * dz + dw * dw;
            float4 o;
            o.x = zv.x + (cv.x - zv.x); o.y = zv.y + (cv.y - zv.y);
            o.z = zv.z + (cv.z - zv.z); o.w = zv.w + (cv.w - zv.w);
            qo[i] = o;
        }
        if (ids_out) ids_out[row] = (float)bid;
    }
    #pragma unroll
    for (int off = 16; off; off >>= 1)
        lsum += __shfl_down_sync(0xffffffffu, lsum, off);
    __shared__ double wp[FTPB / 32];
    if ((tid & 31) == 0) wp[tid >> 5] = (double)lsum;
    __syncthreads();
    if (tid == 0) {
        double s = 0.0;
        #pragma unroll
        for (int w = 0; w < FTPB / 32; w++) s += wp[w];
        g_partial[blockIdx.x] = s;
    }
}

__global__ void vq_finalize(int nblocks, double inv_total, float* loss_out)
{
    __shared__ double sp[256];
    const int tid = threadIdx.x;
    double s = 0.0;
    for (int i = tid; i < nblocks; i += 256) s += g_partial[i];
    sp[tid] = s;
    __syncthreads();
    for (int off = 128; off; off >>= 1) {
        if (tid < off) sp[tid] += sp[tid + off];
        __syncthreads();
    }
    if (tid == 0) {
        double mean = sp[0] * inv_total;
        loss_out[0] = (float)(mean + 0.25 * mean);
    }
}

extern "C" void kernel_launch(void* const* d_in, const int* in_sizes, int n_in,
                              void* d_out, int out_size)
{
    const float* z  = (const float*)d_in[0];
    const float* cb = (const float*)d_in[1];
    const int N = in_sizes[0] / D;
    const int K = in_sizes[1] / D;

    float* out = (float*)d_out;
    float* q_out    = out;
    float* loss_ptr = nullptr;
    float* ids_ptr  = nullptr;
    const long base = (long)N * D;
    if ((long)out_size >= base + 1 + N) { loss_ptr = out + base; ids_ptr = out + base + 1; }
    else if ((long)out_size == base + N) { ids_ptr = out + base; }
    else if ((long)out_size == base + 1) { loss_ptr = out + base; }

    int nblocks;
    if (K == KCODES && (N % MTILE) == 0 && N > 0) {
        const int ntiles = N / MTILE;
        nblocks = ntiles < GRID_MAX ? ntiles : GRID_MAX;
        cudaFuncSetAttribute(vq_mma, cudaFuncAttributeMaxDynamicSharedMemorySize, SMEM_TOTAL);
        vq_mma<<<nblocks, TPB, SMEM_TOTAL>>>(z, cb, N, q_out, ids_ptr);
    } else {
        const size_t smem_bytes = ((size_t)K * ROW_PAD + K) * sizeof(float);
        cudaFuncSetAttribute(vq_ref, cudaFuncAttributeMaxDynamicSharedMemorySize, (int)smem_bytes);
        nblocks = (N + FTPB - 1) / FTPB;
        vq_ref<<<nblocks, FTPB, smem_bytes>>>(z, cb, N, K, q_out, ids_ptr);
    }

    if (loss_ptr) {
        double inv_total = 1.0 / ((double)N * (double)D);
        vq_finalize<<<1, 256>>>(nblocks, inv_total, loss_ptr);
    }
}

// round 13
// speedup vs baseline: 1.1166x; 1.0777x over previous
#include <cuda_runtime.h>
#include <cuda_fp16.h>
#include <cuda_bf16.h>
#include <cstdint>

// ============================================================================
// VQ quantizer: single-pass fp16 mma.sync prefilter (per-row rigorous error
// bound) + provably-exact fp32 argmin rescue.  R12 = R6 hot loop verbatim +
// fused last-block loss finalize + one fewer sync per tile.
// z [N,64] f32, codebook [512,64] f32.
// Outputs (concatenated f32): q_ste [N*64], loss [1], ids [N] (as float).
// ============================================================================

#define D        64
#define KCODES   512
#define MTILE    128
#define TPB      256
#define GRID_MAX 296   // 2 CTAs/SM x 148 SMs

// smem layout (byte offsets); fp16 rows strided 144B => conflict-free frags
#define B_OFF      0        // 512 x 144B fp16 codebook (k-contiguous rows)
#define A_OFF      73728    // 128 x 144B fp16 z tile
#define C2H_OFF    92160    // 512 f32: 0.5*||c||^2
#define Z2S_OFF    94208    // 128 f32: approx ||z||^2 per tile row
#define KID_OFF    94720    // 128 int
#define CN_OFF     95232    // 1 f32: max ||c||
#define SMEM_TOTAL 95744

__device__ double       g_partial[4096];
__device__ unsigned int g_count = 0;

// ---------------- helpers ----------------
__device__ __forceinline__ void mma_fp16(float* c, const uint32_t* a,
                                         uint32_t b0, uint32_t b1) {
    asm volatile(
        "mma.sync.aligned.m16n8k16.row.col.f32.f16.f16.f32 "
        "{%0,%1,%2,%3}, {%4,%5,%6,%7}, {%8,%9}, {%0,%1,%2,%3};"
        : "+f"(c[0]), "+f"(c[1]), "+f"(c[2]), "+f"(c[3])
        : "r"(a[0]), "r"(a[1]), "r"(a[2]), "r"(a[3]), "r"(b0), "r"(b1));
}

// top-3 insert (descending)
__device__ __forceinline__ void ins3(float v, int k, float* tv, int* tk) {
    if (v > tv[2]) {
        if (v > tv[0])      { tv[2]=tv[1]; tk[2]=tk[1]; tv[1]=tv[0]; tk[1]=tk[0]; tv[0]=v; tk[0]=k; }
        else if (v > tv[1]) { tv[2]=tv[1]; tk[2]=tk[1]; tv[1]=v; tk[1]=k; }
        else                { tv[2]=v; tk[2]=k; }
    }
}

// EXACT scorer — replicates round-1 arithmetic (verified rel_err 0.0)
__device__ __forceinline__ float exact_d2(const float4* zr, float z2,
                                          const float* __restrict__ crow) {
    const float4* c4 = (const float4*)crow;
    float4 cv[16];
    #pragma unroll
    for (int i = 0; i < 16; i++) cv[i] = c4[i];
    float c2 = 0.f;
    #pragma unroll
    for (int i = 0; i < 16; i++) {
        c2 += cv[i].x * cv[i].x; c2 += cv[i].y * cv[i].y;
        c2 += cv[i].z * cv[i].z; c2 += cv[i].w * cv[i].w;
    }
    float a0 = 0.f, a1 = 0.f, a2 = 0.f, a3 = 0.f;
    #pragma unroll
    for (int i = 0; i < 16; i++) {
        a0 += zr[i].x * cv[i].x;
        a1 += zr[i].y * cv[i].y;
        a2 += zr[i].z * cv[i].z;
        a3 += zr[i].w * cv[i].w;
    }
    float dot = (a0 + a1) + (a2 + a3);
    return (z2 - 2.0f * dot) + c2;
}

__device__ __forceinline__ float z2_of(const float4* zr) {
    float z2 = 0.f;
    #pragma unroll
    for (int i = 0; i < 16; i++)
        z2 += zr[i].x * zr[i].x + zr[i].y * zr[i].y
            + zr[i].z * zr[i].z + zr[i].w * zr[i].w;
    return z2;
}

// convert 64 f32 -> fp16 row (144B stride), return sum of squares (approx ok)
__device__ __forceinline__ float stage_row_fp16(char* dst, const float4* v) {
    float s = 0.f;
    #pragma unroll
    for (int i = 0; i < 16; i++) {
        float4 a = v[i];
        s += a.x * a.x + a.y * a.y + a.z * a.z + a.w * a.w;
        __half2 h0 = __halves2half2(__float2half_rn(a.x), __float2half_rn(a.y));
        __half2 h1 = __halves2half2(__float2half_rn(a.z), __float2half_rn(a.w));
        uint2 w;
        w.x = *(uint32_t*)&h0;
        w.y = *(uint32_t*)&h1;
        *(uint2*)(dst + i * 8) = w;
    }
    return s;
}

// ============================================================================
// Main kernel: persistent, 2 CTAs/SM, 8 warps, M-tile 128 (1 m16 strip/warp)
// ============================================================================
__global__ __launch_bounds__(TPB, 2)
void vq_mma(const float* __restrict__ z, const float* __restrict__ cb,
            int N, float* __restrict__ q_out, float* __restrict__ ids_out,
            float* __restrict__ loss_out)
{
    extern __shared__ char smem[];
    const int tid  = threadIdx.x;
    const int wid  = tid >> 5;
    const int lane = tid & 31;
    const int qr   = lane >> 2;   // 0..7
    const int qc   = lane & 3;    // 0..3

    float* c2h  = (float*)(smem + C2H_OFF);
    float* z2s  = (float*)(smem + Z2S_OFF);
    int*   kidS = (int*)(smem + KID_OFF);
    float* cnp  = (float*)(smem + CN_OFF);

    // ---- stage codebook once: fp16 rows + 0.5*||c||^2 ----
    for (int n = tid; n < KCODES; n += TPB) {
        float4 cv[16];
        const float4* c4 = (const float4*)(cb + (size_t)n * D);
        #pragma unroll
        for (int i = 0; i < 16; i++) cv[i] = c4[i];
        float s = stage_row_fp16(smem + B_OFF + n * 144, cv);
        c2h[n] = 0.5f * s;
    }
    __syncthreads();
    if (tid < 32) {
        float m = 0.f;
        for (int i = tid; i < KCODES; i += 32) m = fmaxf(m, c2h[i]);
        #pragma unroll
        for (int off = 16; off; off >>= 1)
            m = fmaxf(m, __shfl_xor_sync(0xffffffffu, m, off));
        if (tid == 0) *cnp = sqrtf(2.0f * m);
    }
    __syncthreads();
    const float CNMAX = *cnp;

    const int ntiles = N / MTILE;
    double dsum = 0.0;

    for (int tile = blockIdx.x; tile < ntiles; tile += gridDim.x) {
        // ---- stage A tile: threads 0..127 convert one row each ----
        if (tid < MTILE) {
            float4 zr[16];
            const float4* zp = (const float4*)(z + (size_t)(tile * MTILE + tid) * D);
            #pragma unroll
            for (int i = 0; i < 16; i++) zr[i] = zp[i];
            z2s[tid] = stage_row_fp16(smem + A_OFF + tid * 144, zr);
        }
        __syncthreads();

        // ---- A fragments (hoisted; strip rows wid*16+qr, +8) ----
        uint32_t afr[4][4];
        {
            const int r0b = (wid * 16 + qr) * 144;
            #pragma unroll
            for (int ks = 0; ks < 4; ks++) {
                const int kb = ks * 32 + qc * 4;
                afr[ks][0] = *(const uint32_t*)(smem + A_OFF + r0b + kb);
                afr[ks][1] = *(const uint32_t*)(smem + A_OFF + r0b + 8 * 144 + kb);
                afr[ks][2] = *(const uint32_t*)(smem + A_OFF + r0b + kb + 16);
                afr[ks][3] = *(const uint32_t*)(smem + A_OFF + r0b + 8 * 144 + kb + 16);
            }
        }

        // ---- MMA + per-thread top-3 for 2 row-slots ----
        float tv[2][3];
        int   tk[2][3];
        #pragma unroll
        for (int s = 0; s < 2; s++) {
            tv[s][0] = tv[s][1] = tv[s][2] = -3.4e38f;
            tk[s][0] = tk[s][1] = tk[s][2] = 0;
        }

        for (int ch = 0; ch < 8; ch++) {       // 8 chunks of 64 codes
            float acc[8][4];
            #pragma unroll
            for (int n8 = 0; n8 < 8; n8++)
                #pragma unroll
                for (int f = 0; f < 4; f++) acc[n8][f] = 0.f;

            #pragma unroll
            for (int ks = 0; ks < 4; ks++) {
                const int kb = ks * 32 + qc * 4;
                #pragma unroll
                for (int n8 = 0; n8 < 8; n8++) {
                    const int cbyte = (ch * 64 + n8 * 8 + qr) * 144 + kb;
                    uint32_t b0 = *(const uint32_t*)(smem + B_OFF + cbyte);
                    uint32_t b1 = *(const uint32_t*)(smem + B_OFF + cbyte + 16);
                    mma_fp16(acc[n8], afr[ks], b0, b1);
                }
            }

            #pragma unroll
            for (int n8 = 0; n8 < 8; n8++) {
                const int col0 = ch * 64 + n8 * 8 + qc * 2;
                const float h0 = c2h[col0], h1 = c2h[col0 + 1];
                ins3(acc[n8][0] - h0, col0,     tv[0], tk[0]);
                ins3(acc[n8][1] - h1, col0 + 1, tv[0], tk[0]);
                ins3(acc[n8][2] - h0, col0,     tv[1], tk[1]);
                ins3(acc[n8][3] - h1, col0 + 1, tv[1], tk[1]);
            }
        }

        const float loc3_0 = tv[0][2];
        const float loc3_1 = tv[1][2];

        // ---- quad merge (xor 1, 2) -> global top-3 per slot ----
        #pragma unroll
        for (int off = 1; off <= 2; off <<= 1) {
            #pragma unroll
            for (int s = 0; s < 2; s++) {
                float sv0 = tv[s][0], sv1 = tv[s][1], sv2 = tv[s][2];
                int   sk0 = tk[s][0], sk1 = tk[s][1], sk2 = tk[s][2];
                float ov0 = __shfl_xor_sync(0xffffffffu, sv0, off);
                float ov1 = __shfl_xor_sync(0xffffffffu, sv1, off);
                float ov2 = __shfl_xor_sync(0xffffffffu, sv2, off);
                int   ok0 = __shfl_xor_sync(0xffffffffu, sk0, off);
                int   ok1 = __shfl_xor_sync(0xffffffffu, sk1, off);
                int   ok2 = __shfl_xor_sync(0xffffffffu, sk2, off);
                ins3(ov0, ok0, tv[s], tk[s]);
                ins3(ov1, ok1, tv[s], tk[s]);
                ins3(ov2, ok2, tv[s], tk[s]);
            }
        }

        // ---- per-row rigorous threshold: 2e <= 2^-9 * ||z|| * ||c||max ----
        const int r0 = wid * 16 + qr;
        const float thr0 = sqrtf(z2s[r0])     * CNMAX * 0.001953125f + 5e-4f;
        const float thr1 = sqrtf(z2s[r0 + 8]) * CNMAX * 0.001953125f + 5e-4f;

        unsigned bal0 = __ballot_sync(0xffffffffu, loc3_0 >= tv[0][0] - thr0);
        unsigned bal1 = __ballot_sync(0xffffffffu, loc3_1 >= tv[1][0] - thr1);
        const unsigned qsh = lane & ~3;
        const bool u0 = ((bal0 >> qsh) & 0xFu) != 0;
        const bool u1 = ((bal1 >> qsh) & 0xFu) != 0;

        // ---- finalize: lane qc=0 -> slot 0, qc=1 -> slot 1 ----
        const bool mine = (qc < 2);
        const int  myrow = r0 + qc * 8;                 // valid when mine
        const bool my_unsafe = mine && (qc == 0 ? u0 : u1);
        int kid = 0;

        if (mine && !my_unsafe) {
            float b0v, b1v, b2v, myTHR;
            int   k0v, k1v, k2v;
            if (qc == 0) { b0v=tv[0][0]; b1v=tv[0][1]; b2v=tv[0][2];
                           k0v=tk[0][0]; k1v=tk[0][1]; k2v=tk[0][2]; myTHR=thr0; }
            else         { b0v=tv[1][0]; b1v=tv[1][1]; b2v=tv[1][2];
                           k0v=tk[1][0]; k1v=tk[1][1]; k2v=tk[1][2]; myTHR=thr1; }
            const float thrv = b0v - myTHR;
            int ck[3]; int nc = 1;
            ck[0] = k0v;
            if (b1v >= thrv) ck[nc++] = k1v;
            if (b2v >= thrv) ck[nc++] = k2v;
            if (nc == 1) {
                kid = ck[0];                            // margin proves winner
            } else {
                if (ck[0] > ck[1]) { int t = ck[0]; ck[0] = ck[1]; ck[1] = t; }
                if (nc == 3) {
                    if (ck[1] > ck[2]) { int t = ck[1]; ck[1] = ck[2]; ck[2] = t; }
                    if (ck[0] > ck[1]) { int t = ck[0]; ck[0] = ck[1]; ck[1] = t; }
                }
                const int grow = tile * MTILE + myrow;
                float4 zr[16];
                const float4* zp = (const float4*)(z + (size_t)grow * D);
                #pragma unroll
                for (int i = 0; i < 16; i++) zr[i] = zp[i];
                const float z2 = z2_of(zr);
                float best = 3.402823466e38f; kid = ck[0];
                for (int i = 0; i < nc; i++) {          // ascending k, strict <
                    float d = exact_d2(zr, z2, cb + (size_t)ck[i] * D);
                    if (d < best) { best = d; kid = ck[i]; }
                }
            }
        }

        // ---- warp-cooperative exact scan for unsafe rows (rare) ----
        unsigned need = __ballot_sync(0xffffffffu, my_unsafe);
        while (need) {
            const int src = __ffs(need) - 1;
            need &= need - 1;
            const int rl = __shfl_sync(0xffffffffu, myrow, src);
            const int grow = tile * MTILE + rl;
            float4 zr[16];
            const float4* zp = (const float4*)(z + (size_t)grow * D);
            #pragma unroll
            for (int i = 0; i < 16; i++) zr[i] = zp[i];
            const float z2 = z2_of(zr);
            float best = 3.402823466e38f; int bk = KCODES;
            for (int k = lane; k < KCODES; k += 32) {   // lane-ascending, strict <
                float d = exact_d2(zr, z2, cb + (size_t)k * D);
                if (d < best) { best = d; bk = k; }
            }
            #pragma unroll
            for (int off = 16; off; off >>= 1) {
                float ob = __shfl_xor_sync(0xffffffffu, best, off);
                int   obk = __shfl_xor_sync(0xffffffffu, bk, off);
                if (ob < best || (ob == best && obk < bk)) { best = ob; bk = obk; }
            }
            if (lane == src) kid = bk;
        }

        if (mine) kidS[myrow] = kid;
        __syncthreads();

        // ---- epilogue: threads 0..127, row tid ----
        // (no end-of-loop sync: next SYNC after staging orders everything;
        //  epilogue reads only kidS/global, staging writes only A/z2s)
        if (tid < MTILE) {
            const int grow = tile * MTILE + tid;
            const int k = kidS[tid];
            float4 zr[16];
            const float4* zp = (const float4*)(z + (size_t)grow * D);
            #pragma unroll
            for (int i = 0; i < 16; i++) zr[i] = zp[i];
            const float4* q4 = (const float4*)(cb + (size_t)k * D);
            float4* qo = (float4*)(q_out + (size_t)grow * D);
            float lsum = 0.f;
            #pragma unroll
            for (int i = 0; i < 16; i++) {
                float4 cv = q4[i];
                float4 zv = zr[i];
                float dx = zv.x - cv.x, dy = zv.y - cv.y;
                float dz = zv.z - cv.z, dw = zv.w - cv.w;
                lsum += dx * dx + dy * dy + dz * dz + dw * dw;
                float4 o;
                o.x = zv.x + (cv.x - zv.x);   // fl(z + fl(q - z)), reference STE
                o.y = zv.y + (cv.y - zv.y);
                o.z = zv.z + (cv.z - zv.z);
                o.w = zv.w + (cv.w - zv.w);
                qo[i] = o;
            }
            if (ids_out) ids_out[grow] = (float)k;
            dsum += (double)lsum;
        }
    }

    // ---- deterministic per-CTA loss reduction ----
    __syncthreads();
    double* red = (double*)(smem + B_OFF);   // codebook region reusable now
    red[tid] = dsum;
    __syncthreads();
    if (tid == 0) {
        double s = 0.0;
        for (int i = 0; i < TPB; i++) s += red[i];
        g_partial[blockIdx.x] = s;
    }

    // ---- fused finalize: last CTA computes the loss (deterministic order) ----
    if (loss_out) {
        __shared__ unsigned s_last;
        if (tid == 0) {
            __threadfence();
            unsigned p = atomicAdd(&g_count, 1u);
            s_last = (p == gridDim.x - 1) ? 1u : 0u;
        }
        __syncthreads();
        if (s_last) {
            __threadfence();
            double s = 0.0;
            for (int i = tid; i < (int)gridDim.x; i += TPB) s += g_partial[i];
            double* sp = (double*)(smem + B_OFF);
            sp[tid] = s;
            __syncthreads();
            for (int off = TPB / 2; off; off >>= 1) {
                if (tid < off) sp[tid] += sp[tid + off];
                __syncthreads();
            }
            if (tid == 0) {
                double mean = sp[0] / ((double)N * (double)D);
                loss_out[0] = (float)(mean + 0.25 * mean);
                g_count = 0;                 // reset for graph replay
            }
        }
    }
}

// ============================================================================
// Generic fallback (round-2 kernel) for unexpected shapes
// ============================================================================
#define FTPB 256
#define ROW_PAD 68
__global__ __launch_bounds__(FTPB) void vq_ref(
    const float* __restrict__ z, const float* __restrict__ cb,
    int N, int K, float* __restrict__ q_out, float* __restrict__ ids_out)
{
    extern __shared__ float fsm[];
    float* cbs = fsm;
    float* c2  = fsm + (size_t)K * ROW_PAD;
    const int tid = threadIdx.x;
    const float4* cb4 = (const float4*)cb;
    const int nvec = K * (D / 4);
    for (int idx = tid; idx < nvec; idx += FTPB) {
        int k = idx >> 4, c = idx & 15;
        *(float4*)&cbs[k * ROW_PAD + c * 4] = cb4[idx];
    }
    __syncthreads();
    for (int k = tid; k < K; k += FTPB) {
        const float* r = &cbs[k * ROW_PAD];
        float s = 0.f;
        #pragma unroll
        for (int i = 0; i < D; i++) s += r[i] * r[i];
        c2[k] = s;
    }
    __syncthreads();
    const int row = blockIdx.x * FTPB + tid;
    float lsum = 0.f;
    if (row < N) {
        float4 zr[16];
        const float4* zp = (const float4*)(z + (size_t)row * D);
        #pragma unroll
        for (int i = 0; i < 16; i++) zr[i] = zp[i];
        float z2 = 0.f;
        #pragma unroll
        for (int i = 0; i < 16; i++)
            z2 += zr[i].x * zr[i].x + zr[i].y * zr[i].y
                + zr[i].z * zr[i].z + zr[i].w * zr[i].w;
        float best = 3.402823466e38f; int bid = 0;
        for (int k = 0; k < K; k++) {
            const float4* crow = (const float4*)&cbs[k * ROW_PAD];
            float a0 = 0.f, a1 = 0.f, a2 = 0.f, a3 = 0.f;
            #pragma unroll
            for (int i = 0; i < 16; i++) {
                float4 cv = crow[i];
                a0 += zr[i].x * cv.x; a1 += zr[i].y * cv.y;
                a2 += zr[i].z * cv.z; a3 += zr[i].w * cv.w;
            }
            float dot = (a0 + a1) + (a2 + a3);
            float d = (z2 - 2.0f * dot) + c2[k];
            if (d < best) { best = d; bid = k; }
        }
        const float4* crow = (const float4*)&cbs[bid * ROW_PAD];
        float4* qo = (float4*)(q_out + (size_t)row * D);
        #pragma unroll
        for (int i = 0; i < 16; i++) {
            float4 cv = crow[i];
            float4 zv = zr[i];
            float dx = zv.x - cv.x, dy = zv.y - cv.y;
            float dz = zv.z - cv.z, dw = zv.w - cv.w;
            lsum += dx * dx + dy * dy + dz * dz + dw * dw;
            float4 o;
            o.x = zv.x + (cv.x - zv.x); o.y = zv.y + (cv.y - zv.y);
            o.z = zv.z + (cv.z - zv.z); o.w = zv.w + (cv.w - zv.w);
            qo[i] = o;
        }
        if (ids_out) ids_out[row] = (float)bid;
    }
    #pragma unroll
    for (int off = 16; off; off >>= 1)
        lsum += __shfl_down_sync(0xffffffffu, lsum, off);
    __shared__ double wp[FTPB / 32];
    if ((tid & 31) == 0) wp[tid >> 5] = (double)lsum;
    __syncthreads();
    if (tid == 0) {
        double s = 0.0;
        #pragma unroll
        for (int w = 0; w < FTPB / 32; w++) s += wp[w];
        g_partial[blockIdx.x] = s;
    }
}

__global__ void vq_finalize(int nblocks, double inv_total, float* loss_out)
{
    __shared__ double sp[256];
    const int tid = threadIdx.x;
    double s = 0.0;
    for (int i = tid; i < nblocks; i += 256) s += g_partial[i];
    sp[tid] = s;
    __syncthreads();
    for (int off = 128; off; off >>= 1) {
        if (tid < off) sp[tid] += sp[tid + off];
        __syncthreads();
    }
    if (tid == 0) {
        double mean = sp[0] * inv_total;
        loss_out[0] = (float)(mean + 0.25 * mean);
    }
}

extern "C" void kernel_launch(void* const* d_in, const int* in_sizes, int n_in,
                              void* d_out, int out_size)
{
    const float* z  = (const float*)d_in[0];
    const float* cb = (const float*)d_in[1];
    const int N = in_sizes[0] / D;
    const int K = in_sizes[1] / D;

    float* out = (float*)d_out;
    float* q_out    = out;
    float* loss_ptr = nullptr;
    float* ids_ptr  = nullptr;
    const long base = (long)N * D;
    if ((long)out_size >= base + 1 + N) { loss_ptr = out + base; ids_ptr = out + base + 1; }
    else if ((long)out_size == base + N) { ids_ptr = out + base; }
    else if ((long)out_size == base + 1) { loss_ptr = out + base; }

    if (K == KCODES && (N % MTILE) == 0 && N > 0) {
        const int ntiles = N / MTILE;
        const int nblocks = ntiles < GRID_MAX ? ntiles : GRID_MAX;
        cudaFuncSetAttribute(vq_mma, cudaFuncAttributeMaxDynamicSharedMemorySize, SMEM_TOTAL);
        vq_mma<<<nblocks, TPB, SMEM_TOTAL>>>(z, cb, N, q_out, ids_ptr, loss_ptr);
    } else {
        const size_t smem_bytes = ((size_t)K * ROW_PAD + K) * sizeof(float);
        cudaFuncSetAttribute(vq_ref, cudaFuncAttributeMaxDynamicSharedMemorySize, (int)smem_bytes);
        const int nblocks = (N + FTPB - 1) / FTPB;
        vq_ref<<<nblocks, FTPB, smem_bytes>>>(z, cb, N, K, q_out, ids_ptr);
        if (loss_ptr) {
            double inv_total = 1.0 / ((double)N * (double)D);
            vq_finalize<<<1, 256>>>(nblocks, inv_total, loss_ptr);
        }
    }
}

// round 14
// speedup vs baseline: 1.1416x; 1.0224x over previous
#include <cuda_runtime.h>
#include <cuda_fp16.h>
#include <cuda_bf16.h>
#include <cstdint>

// ============================================================================
// VQ quantizer: single-pass fp16 mma.sync prefilter (per-row rigorous error
// bound) + provably-exact fp32 argmin rescue.
// R13: permuted B layout -> LDS.128 fragment loads (4x fewer load issues),
// accumulators init to -0.5*||c||^2 (no per-chunk FADD/LDS), fused finalize.
// z [N,64] f32, codebook [512,64] f32.
// Outputs (concatenated f32): q_ste [N*64], loss [1], ids [N] (as float).
// ============================================================================

#define D        64
#define KCODES   512
#define MTILE    128
#define TPB      256
#define GRID_MAX 296   // 2 CTAs/SM x 148 SMs

// smem layout (byte offsets); rows strided 144B => conflict-free LDS.128 frags
#define B_OFF      0        // 512 x 144B fp16 codebook rows (PERMUTED words)
#define A_OFF      73728    // 128 x 144B fp16 z tile (row-major words)
#define C2H_OFF    92160    // 512 f32: +0.5*||c||^2
#define C2N_OFF    94208    // 512 f32: -0.5*||c||^2
#define Z2S_OFF    96256    // 128 f32: approx ||z||^2 per tile row
#define KID_OFF    96768    // 128 int
#define CN_OFF     97280    // 1 f32: max ||c||
#define SMEM_TOTAL 97408

__device__ double       g_partial[4096];
__device__ unsigned int g_count = 0;

// ---------------- helpers ----------------
__device__ __forceinline__ void mma_fp16(float* c, const uint32_t* a,
                                         uint32_t b0, uint32_t b1) {
    asm volatile(
        "mma.sync.aligned.m16n8k16.row.col.f32.f16.f16.f32 "
        "{%0,%1,%2,%3}, {%4,%5,%6,%7}, {%8,%9}, {%0,%1,%2,%3};"
        : "+f"(c[0]), "+f"(c[1]), "+f"(c[2]), "+f"(c[3])
        : "r"(a[0]), "r"(a[1]), "r"(a[2]), "r"(a[3]), "r"(b0), "r"(b1));
}

// top-3 insert (descending)
__device__ __forceinline__ void ins3(float v, int k, float* tv, int* tk) {
    if (v > tv[2]) {
        if (v > tv[0])      { tv[2]=tv[1]; tk[2]=tk[1]; tv[1]=tv[0]; tk[1]=tk[0]; tv[0]=v; tk[0]=k; }
        else if (v > tv[1]) { tv[2]=tv[1]; tk[2]=tk[1]; tv[1]=v; tk[1]=k; }
        else                { tv[2]=v; tk[2]=k; }
    }
}

// EXACT scorer — replicates round-1 arithmetic (verified rel_err 0.0)
__device__ __forceinline__ float exact_d2(const float4* zr, float z2,
                                          const float* __restrict__ crow) {
    const float4* c4 = (const float4*)crow;
    float4 cv[16];
    #pragma unroll
    for (int i = 0; i < 16; i++) cv[i] = c4[i];
    float c2 = 0.f;
    #pragma unroll
    for (int i = 0; i < 16; i++) {
        c2 += cv[i].x * cv[i].x; c2 += cv[i].y * cv[i].y;
        c2 += cv[i].z * cv[i].z; c2 += cv[i].w * cv[i].w;
    }
    float a0 = 0.f, a1 = 0.f, a2 = 0.f, a3 = 0.f;
    #pragma unroll
    for (int i = 0; i < 16; i++) {
        a0 += zr[i].x * cv[i].x;
        a1 += zr[i].y * cv[i].y;
        a2 += zr[i].z * cv[i].z;
        a3 += zr[i].w * cv[i].w;
    }
    float dot = (a0 + a1) + (a2 + a3);
    return (z2 - 2.0f * dot) + c2;
}

__device__ __forceinline__ float z2_of(const float4* zr) {
    float z2 = 0.f;
    #pragma unroll
    for (int i = 0; i < 16; i++)
        z2 += zr[i].x * zr[i].x + zr[i].y * zr[i].y
            + zr[i].z * zr[i].z + zr[i].w * zr[i].w;
    return z2;
}

__device__ __forceinline__ uint32_t packh2(float x, float y) {
    __nv_half2_raw h2 = __halves2half2(__float2half_rn(x), __float2half_rn(y));
    return *(uint32_t*)&h2;
}

// A row: convert 64 f32 -> fp16, row-major words, return sum of squares
__device__ __forceinline__ float stage_row_fp16(char* dst, const float4* v) {
    float s = 0.f;
    #pragma unroll
    for (int i = 0; i < 16; i++) {
        float4 a = v[i];
        s += a.x * a.x + a.y * a.y + a.z * a.z + a.w * a.w;
        uint2 w;
        w.x = packh2(a.x, a.y);
        w.y = packh2(a.z, a.w);
        *(uint2*)(dst + i * 8) = w;
    }
    return s;
}

// B row: convert + store PERMUTED: new word p holds orig word (p>>3) + 4*(p&7)
// so thread (qr,qc) reads its 8 fragment words contiguously at qc*32 bytes.
__device__ __forceinline__ float stage_row_b_perm(char* dst, const float4* v) {
    float s = 0.f;
    uint32_t w[32];
    #pragma unroll
    for (int i = 0; i < 16; i++) {
        float4 a = v[i];
        s += a.x * a.x + a.y * a.y + a.z * a.z + a.w * a.w;
        w[2 * i]     = packh2(a.x, a.y);
        w[2 * i + 1] = packh2(a.z, a.w);
    }
    *(uint4*)(dst +   0) = make_uint4(w[0],  w[4],  w[8],  w[12]);
    *(uint4*)(dst +  16) = make_uint4(w[16], w[20], w[24], w[28]);
    *(uint4*)(dst +  32) = make_uint4(w[1],  w[5],  w[9],  w[13]);
    *(uint4*)(dst +  48) = make_uint4(w[17], w[21], w[25], w[29]);
    *(uint4*)(dst +  64) = make_uint4(w[2],  w[6],  w[10], w[14]);
    *(uint4*)(dst +  80) = make_uint4(w[18], w[22], w[26], w[30]);
    *(uint4*)(dst +  96) = make_uint4(w[3],  w[7],  w[11], w[15]);
    *(uint4*)(dst + 112) = make_uint4(w[19], w[23], w[27], w[31]);
    return s;
}

// ============================================================================
// Main kernel: persistent, 2 CTAs/SM, 8 warps, M-tile 128 (1 m16 strip/warp)
// ============================================================================
__global__ __launch_bounds__(TPB, 2)
void vq_mma(const float* __restrict__ z, const float* __restrict__ cb,
            int N, float* __restrict__ q_out, float* __restrict__ ids_out,
            float* __restrict__ loss_out)
{
    extern __shared__ char smem[];
    const int tid  = threadIdx.x;
    const int wid  = tid >> 5;
    const int lane = tid & 31;
    const int qr   = lane >> 2;   // 0..7
    const int qc   = lane & 3;    // 0..3

    float* c2h  = (float*)(smem + C2H_OFF);
    float* c2n  = (float*)(smem + C2N_OFF);
    float* z2s  = (float*)(smem + Z2S_OFF);
    int*   kidS = (int*)(smem + KID_OFF);
    float* cnp  = (float*)(smem + CN_OFF);

    // ---- stage codebook once: permuted fp16 rows + +-0.5*||c||^2 ----
    for (int n = tid; n < KCODES; n += TPB) {
        float4 cv[16];
        const float4* c4 = (const float4*)(cb + (size_t)n * D);
        #pragma unroll
        for (int i = 0; i < 16; i++) cv[i] = c4[i];
        float s = stage_row_b_perm(smem + B_OFF + n * 144, cv);
        c2h[n] =  0.5f * s;
        c2n[n] = -0.5f * s;
    }
    __syncthreads();
    if (tid < 32) {
        float m = 0.f;
        for (int i = tid; i < KCODES; i += 32) m = fmaxf(m, c2h[i]);
        #pragma unroll
        for (int off = 16; off; off >>= 1)
            m = fmaxf(m, __shfl_xor_sync(0xffffffffu, m, off));
        if (tid == 0) *cnp = sqrtf(2.0f * m);
    }
    __syncthreads();
    const float CNMAX = *cnp;

    const int ntiles = N / MTILE;
    double dsum = 0.0;

    for (int tile = blockIdx.x; tile < ntiles; tile += gridDim.x) {
        // ---- stage A tile: threads 0..127 convert one row each ----
        if (tid < MTILE) {
            float4 zr[16];
            const float4* zp = (const float4*)(z + (size_t)(tile * MTILE + tid) * D);
            #pragma unroll
            for (int i = 0; i < 16; i++) zr[i] = zp[i];
            z2s[tid] = stage_row_fp16(smem + A_OFF + tid * 144, zr);
        }
        __syncthreads();

        // ---- A fragments (hoisted; strip rows wid*16+qr, +8) ----
        uint32_t afr[4][4];
        {
            const int r0b = (wid * 16 + qr) * 144;
            #pragma unroll
            for (int ks = 0; ks < 4; ks++) {
                const int kb = ks * 32 + qc * 4;
                afr[ks][0] = *(const uint32_t*)(smem + A_OFF + r0b + kb);
                afr[ks][1] = *(const uint32_t*)(smem + A_OFF + r0b + 8 * 144 + kb);
                afr[ks][2] = *(const uint32_t*)(smem + A_OFF + r0b + kb + 16);
                afr[ks][3] = *(const uint32_t*)(smem + A_OFF + r0b + 8 * 144 + kb + 16);
            }
        }

        // ---- MMA + per-thread top-3 for 2 row-slots ----
        float tv[2][3];
        int   tk[2][3];
        #pragma unroll
        for (int s = 0; s < 2; s++) {
            tv[s][0] = tv[s][1] = tv[s][2] = -3.4e38f;
            tk[s][0] = tk[s][1] = tk[s][2] = 0;
        }

        for (int grp = 0; grp < 16; grp++) {   // 16 groups of 32 codes
            float acc[4][4];
            uint4 ra[4], rb[4];
            #pragma unroll
            for (int c = 0; c < 4; c++) {
                const int col0 = grp * 32 + c * 8 + qc * 2;
                const float2 nh = *(const float2*)&c2n[col0];
                acc[c][0] = nh.x; acc[c][1] = nh.y;   // init = -0.5*||c||^2
                acc[c][2] = nh.x; acc[c][3] = nh.y;
                const char* bp = smem + B_OFF
                               + (grp * 32 + c * 8 + qr) * 144 + qc * 32;
                ra[c] = *(const uint4*)(bp);
                rb[c] = *(const uint4*)(bp + 16);
            }
            #pragma unroll
            for (int c = 0; c < 4; c++) mma_fp16(acc[c], afr[0], ra[c].x, ra[c].y);
            #pragma unroll
            for (int c = 0; c < 4; c++) mma_fp16(acc[c], afr[1], ra[c].z, ra[c].w);
            #pragma unroll
            for (int c = 0; c < 4; c++) mma_fp16(acc[c], afr[2], rb[c].x, rb[c].y);
            #pragma unroll
            for (int c = 0; c < 4; c++) mma_fp16(acc[c], afr[3], rb[c].z, rb[c].w);

            #pragma unroll
            for (int c = 0; c < 4; c++) {
                const int col0 = grp * 32 + c * 8 + qc * 2;
                ins3(acc[c][0], col0,     tv[0], tk[0]);
                ins3(acc[c][1], col0 + 1, tv[0], tk[0]);
                ins3(acc[c][2], col0,     tv[1], tk[1]);
                ins3(acc[c][3], col0 + 1, tv[1], tk[1]);
            }
        }

        const float loc3_0 = tv[0][2];
        const float loc3_1 = tv[1][2];

        // ---- quad merge (xor 1, 2) -> global top-3 per slot ----
        #pragma unroll
        for (int off = 1; off <= 2; off <<= 1) {
            #pragma unroll
            for (int s = 0; s < 2; s++) {
                float sv0 = tv[s][0], sv1 = tv[s][1], sv2 = tv[s][2];
                int   sk0 = tk[s][0], sk1 = tk[s][1], sk2 = tk[s][2];
                float ov0 = __shfl_xor_sync(0xffffffffu, sv0, off);
                float ov1 = __shfl_xor_sync(0xffffffffu, sv1, off);
                float ov2 = __shfl_xor_sync(0xffffffffu, sv2, off);
                int   ok0 = __shfl_xor_sync(0xffffffffu, sk0, off);
                int   ok1 = __shfl_xor_sync(0xffffffffu, sk1, off);
                int   ok2 = __shfl_xor_sync(0xffffffffu, sk2, off);
                ins3(ov0, ok0, tv[s], tk[s]);
                ins3(ov1, ok1, tv[s], tk[s]);
                ins3(ov2, ok2, tv[s], tk[s]);
            }
        }

        // ---- per-row rigorous threshold: 2e <= 2^-9 * ||z|| * ||c||max ----
        const int r0 = wid * 16 + qr;
        const float thr0 = sqrtf(z2s[r0])     * CNMAX * 0.001953125f + 5e-4f;
        const float thr1 = sqrtf(z2s[r0 + 8]) * CNMAX * 0.001953125f + 5e-4f;

        unsigned bal0 = __ballot_sync(0xffffffffu, loc3_0 >= tv[0][0] - thr0);
        unsigned bal1 = __ballot_sync(0xffffffffu, loc3_1 >= tv[1][0] - thr1);
        const unsigned qsh = lane & ~3;
        const bool u0 = ((bal0 >> qsh) & 0xFu) != 0;
        const bool u1 = ((bal1 >> qsh) & 0xFu) != 0;

        // ---- finalize: lane qc=0 -> slot 0, qc=1 -> slot 1 ----
        const bool mine = (qc < 2);
        const int  myrow = r0 + qc * 8;                 // valid when mine
        const bool my_unsafe = mine && (qc == 0 ? u0 : u1);
        int kid = 0;

        if (mine && !my_unsafe) {
            float b0v, b1v, b2v, myTHR;
            int   k0v, k1v, k2v;
            if (qc == 0) { b0v=tv[0][0]; b1v=tv[0][1]; b2v=tv[0][2];
                           k0v=tk[0][0]; k1v=tk[0][1]; k2v=tk[0][2]; myTHR=thr0; }
            else         { b0v=tv[1][0]; b1v=tv[1][1]; b2v=tv[1][2];
                           k0v=tk[1][0]; k1v=tk[1][1]; k2v=tk[1][2]; myTHR=thr1; }
            const float thrv = b0v - myTHR;
            int ck[3]; int nc = 1;
            ck[0] = k0v;
            if (b1v >= thrv) ck[nc++] = k1v;
            if (b2v >= thrv) ck[nc++] = k2v;
            if (nc == 1) {
                kid = ck[0];                            // margin proves winner
            } else {
                if (ck[0] > ck[1]) { int t = ck[0]; ck[0] = ck[1]; ck[1] = t; }
                if (nc == 3) {
                    if (ck[1] > ck[2]) { int t = ck[1]; ck[1] = ck[2]; ck[2] = t; }
                    if (ck[0] > ck[1]) { int t = ck[0]; ck[0] = ck[1]; ck[1] = t; }
                }
                const int grow = tile * MTILE + myrow;
                float4 zr[16];
                const float4* zp = (const float4*)(z + (size_t)grow * D);
                #pragma unroll
                for (int i = 0; i < 16; i++) zr[i] = zp[i];
                const float z2 = z2_of(zr);
                float best = 3.402823466e38f; kid = ck[0];
                for (int i = 0; i < nc; i++) {          // ascending k, strict <
                    float d = exact_d2(zr, z2, cb + (size_t)ck[i] * D);
                    if (d < best) { best = d; kid = ck[i]; }
                }
            }
        }

        // ---- warp-cooperative exact scan for unsafe rows (rare) ----
        unsigned need = __ballot_sync(0xffffffffu, my_unsafe);
        while (need) {
            const int src = __ffs(need) - 1;
            need &= need - 1;
            const int rl = __shfl_sync(0xffffffffu, myrow, src);
            const int grow = tile * MTILE + rl;
            float4 zr[16];
            const float4* zp = (const float4*)(z + (size_t)grow * D);
            #pragma unroll
            for (int i = 0; i < 16; i++) zr[i] = zp[i];
            const float z2 = z2_of(zr);
            float best = 3.402823466e38f; int bk = KCODES;
            for (int k = lane; k < KCODES; k += 32) {   // lane-ascending, strict <
                float d = exact_d2(zr, z2, cb + (size_t)k * D);
                if (d < best) { best = d; bk = k; }
            }
            #pragma unroll
            for (int off = 16; off; off >>= 1) {
                float ob = __shfl_xor_sync(0xffffffffu, best, off);
                int   obk = __shfl_xor_sync(0xffffffffu, bk, off);
                if (ob < best || (ob == best && obk < bk)) { best = ob; bk = obk; }
            }
            if (lane == src) kid = bk;
        }

        if (mine) kidS[myrow] = kid;
        __syncthreads();

        // ---- epilogue: threads 0..127, row tid (no end-of-loop sync needed:
        //  epilogue reads kidS/global only; staging writes A/z2s only) ----
        if (tid < MTILE) {
            const int grow = tile * MTILE + tid;
            const int k = kidS[tid];
            float4 zr[16];
            const float4* zp = (const float4*)(z + (size_t)grow * D);
            #pragma unroll
            for (int i = 0; i < 16; i++) zr[i] = zp[i];
            const float4* q4 = (const float4*)(cb + (size_t)k * D);
            float4* qo = (float4*)(q_out + (size_t)grow * D);
            float lsum = 0.f;
            #pragma unroll
            for (int i = 0; i < 16; i++) {
                float4 cv = q4[i];
                float4 zv = zr[i];
                float dx = zv.x - cv.x, dy = zv.y - cv.y;
                float dz = zv.z - cv.z, dw = zv.w - cv.w;
                lsum += dx * dx + dy * dy + dz * dz + dw * dw;
                float4 o;
                o.x = zv.x + (cv.x - zv.x);   // fl(z + fl(q - z)), reference STE
                o.y = zv.y + (cv.y - zv.y);
                o.z = zv.z + (cv.z - zv.z);
                o.w = zv.w + (cv.w - zv.w);
                qo[i] = o;
            }
            if (ids_out) ids_out[grow] = (float)k;
            dsum += (double)lsum;
        }
    }

    // ---- deterministic per-CTA loss reduction ----
    __syncthreads();
    double* red = (double*)(smem + B_OFF);   // codebook region reusable now
    red[tid] = dsum;
    __syncthreads();
    if (tid == 0) {
        double s = 0.0;
        for (int i = 0; i < TPB; i++) s += red[i];
        g_partial[blockIdx.x] = s;
    }

    // ---- fused finalize: last CTA computes the loss (deterministic order) ----
    if (loss_out) {
        __shared__ unsigned s_last;
        if (tid == 0) {
            __threadfence();
            unsigned p = atomicAdd(&g_count, 1u);
            s_last = (p == gridDim.x - 1) ? 1u : 0u;
        }
        __syncthreads();
        if (s_last) {
            __threadfence();
            double s = 0.0;
            for (int i = tid; i < (int)gridDim.x; i += TPB) s += g_partial[i];
            double* sp = (double*)(smem + B_OFF);
            sp[tid] = s;
            __syncthreads();
            for (int off = TPB / 2; off; off >>= 1) {
                if (tid < off) sp[tid] += sp[tid + off];
                __syncthreads();
            }
            if (tid == 0) {
                double mean = sp[0] / ((double)N * (double)D);
                loss_out[0] = (float)(mean + 0.25 * mean);
                g_count = 0;                 // reset for graph replay
            }
        }
    }
}

// ============================================================================
// Generic fallback (round-2 kernel) for unexpected shapes
// ============================================================================
#define FTPB 256
#define ROW_PAD 68
__global__ __launch_bounds__(FTPB) void vq_ref(
    const float* __restrict__ z, const float* __restrict__ cb,
    int N, int K, float* __restrict__ q_out, float* __restrict__ ids_out)
{
    extern __shared__ float fsm[];
    float* cbs = fsm;
    float* c2  = fsm + (size_t)K * ROW_PAD;
    const int tid = threadIdx.x;
    const float4* cb4 = (const float4*)cb;
    const int nvec = K * (D / 4);
    for (int idx = tid; idx < nvec; idx += FTPB) {
        int k = idx >> 4, c = idx & 15;
        *(float4*)&cbs[k * ROW_PAD + c * 4] = cb4[idx];
    }
    __syncthreads();
    for (int k = tid; k < K; k += FTPB) {
        const float* r = &cbs[k * ROW_PAD];
        float s = 0.f;
        #pragma unroll
        for (int i = 0; i < D; i++) s += r[i] * r[i];
        c2[k] = s;
    }
    __syncthreads();
    const int row = blockIdx.x * FTPB + tid;
    float lsum = 0.f;
    if (row < N) {
        float4 zr[16];
        const float4* zp = (const float4*)(z + (size_t)row * D);
        #pragma unroll
        for (int i = 0; i < 16; i++) zr[i] = zp[i];
        float z2 = 0.f;
        #pragma unroll
        for (int i = 0; i < 16; i++)
            z2 += zr[i].x * zr[i].x + zr[i].y * zr[i].y
                + zr[i].z * zr[i].z + zr[i].w * zr[i].w;
        float best = 3.402823466e38f; int bid = 0;
        for (int k = 0; k < K; k++) {
            const float4* crow = (const float4*)&cbs[k * ROW_PAD];
            float a0 = 0.f, a1 = 0.f, a2 = 0.f, a3 = 0.f;
            #pragma unroll
            for (int i = 0; i < 16; i++) {
                float4 cv = crow[i];
                a0 += zr[i].x * cv.x; a1 += zr[i].y * cv.y;
                a2 += zr[i].z * cv.z; a3 += zr[i].w * cv.w;
            }
            float dot = (a0 + a1) + (a2 + a3);
            float d = (z2 - 2.0f * dot) + c2[k];
            if (d < best) { best = d; bid = k; }
        }
        const float4* crow = (const float4*)&cbs[bid * ROW_PAD];
        float4* qo = (float4*)(q_out + (size_t)row * D);
        #pragma unroll
        for (int i = 0; i < 16; i++) {
            float4 cv = crow[i];
            float4 zv = zr[i];
            float dx = zv.x - cv.x, dy = zv.y - cv.y;
            float dz = zv.z - cv.z, dw = zv.w - cv.w;
            lsum += dx * dx + dy * dy + dz * dz + dw * dw;
            float4 o;
            o.x = zv.x + (cv.x - zv.x); o.y = zv.y + (cv.y - zv.y);
            o.z = zv.z + (cv.z - zv.z); o.w = zv.w + (cv.w - zv.w);
            qo[i] = o;
        }
        if (ids_out) ids_out[row] = (float)bid;
    }
    #pragma unroll
    for (int off = 16; off; off >>= 1)
        lsum += __shfl_down_sync(0xffffffffu, lsum, off);
    __shared__ double wp[FTPB / 32];
    if ((tid & 31) == 0) wp[tid >> 5] = (double)lsum;
    __syncthreads();
    if (tid == 0) {
        double s = 0.0;
        #pragma unroll
        for (int w = 0; w < FTPB / 32; w++) s += wp[w];
        g_partial[blockIdx.x] = s;
    }
}

__global__ void vq_finalize(int nblocks, double inv_total, float* loss_out)
{
    __shared__ double sp[256];
    const int tid = threadIdx.x;
    double s = 0.0;
    for (int i = tid; i < nblocks; i += 256) s += g_partial[i];
    sp[tid] = s;
    __syncthreads();
    for (int off = 128; off; off >>= 1) {
        if (tid < off) sp[tid] += sp[tid + off];
        __syncthreads();
    }
    if (tid == 0) {
        double mean = sp[0] * inv_total;
        loss_out[0] = (float)(mean + 0.25 * mean);
    }
}

extern "C" void kernel_launch(void* const* d_in, const int* in_sizes, int n_in,
                              void* d_out, int out_size)
{
    const float* z  = (const float*)d_in[0];
    const float* cb = (const float*)d_in[1];
    const int N = in_sizes[0] / D;
    const int K = in_sizes[1] / D;

    float* out = (float*)d_out;
    float* q_out    = out;
    float* loss_ptr = nullptr;
    float* ids_ptr  = nullptr;
    const long base = (long)N * D;
    if ((long)out_size >= base + 1 + N) { loss_ptr = out + base; ids_ptr = out + base + 1; }
    else if ((long)out_size == base + N) { ids_ptr = out + base; }
    else if ((long)out_size == base + 1) { loss_ptr = out + base; }

    if (K == KCODES && (N % MTILE) == 0 && N > 0) {
        const int ntiles = N / MTILE;
        const int nblocks = ntiles < GRID_MAX ? ntiles : GRID_MAX;
        cudaFuncSetAttribute(vq_mma, cudaFuncAttributeMaxDynamicSharedMemorySize, SMEM_TOTAL);
        vq_mma<<<nblocks, TPB, SMEM_TOTAL>>>(z, cb, N, q_out, ids_ptr, loss_ptr);
    } else {
        const size_t smem_bytes = ((size_t)K * ROW_PAD + K) * sizeof(float);
        cudaFuncSetAttribute(vq_ref, cudaFuncAttributeMaxDynamicSharedMemorySize, (int)smem_bytes);
        const int nblocks = (N + FTPB - 1) / FTPB;
        vq_ref<<<nblocks, FTPB, smem_bytes>>>(z, cb, N, K, q_out, ids_ptr);
        if (loss_ptr) {
            double inv_total = 1.0 / ((double)N * (double)D);
            vq_finalize<<<1, 256>>>(nblocks, inv_total, loss_ptr);
        }
    }
}

// round 15
// speedup vs baseline: 1.5529x; 1.3603x over previous
#include <cuda_runtime.h>
#include <cuda_fp16.h>
#include <cuda_bf16.h>
#include <cstdint>

// ============================================================================
// VQ quantizer: single-pass fp16 mma.sync prefilter (per-row rigorous error
// bound) + provably-exact fp32 argmin rescue.
// R14: branchless packed-key top-3 (IMNMX, value+index in one reg) replaces
// FSETP-chained float inserts — cuts the scan critical path ~3x.
// z [N,64] f32, codebook [512,64] f32.
// Outputs (concatenated f32): q_ste [N*64], loss [1], ids [N] (as float).
// ============================================================================

#define D        64
#define KCODES   512
#define MTILE    128
#define TPB      256
#define GRID_MAX 296   // 2 CTAs/SM x 148 SMs

// smem layout (byte offsets); rows strided 144B => conflict-free LDS.128 frags
#define B_OFF      0        // 512 x 144B fp16 codebook rows (PERMUTED words)
#define A_OFF      73728    // 128 x 144B fp16 z tile (row-major words)
#define C2H_OFF    92160    // 512 f32: +0.5*||c||^2
#define C2N_OFF    94208    // 512 f32: -0.5*||c||^2
#define Z2S_OFF    96256    // 128 f32: approx ||z||^2 per tile row
#define KID_OFF    96768    // 128 int
#define CN_OFF     97280    // 1 f32: max ||c||
#define SMEM_TOTAL 97408

#define KEYMASK 0xFFFFFE00u   // top 23 bits = biased score, low 9 = 511-k

__device__ double       g_partial[4096];
__device__ unsigned int g_count = 0;

// ---------------- helpers ----------------
__device__ __forceinline__ void mma_fp16(float* c, const uint32_t* a,
                                         uint32_t b0, uint32_t b1) {
    asm volatile(
        "mma.sync.aligned.m16n8k16.row.col.f32.f16.f16.f32 "
        "{%0,%1,%2,%3}, {%4,%5,%6,%7}, {%8,%9}, {%0,%1,%2,%3};"
        : "+f"(c[0]), "+f"(c[1]), "+f"(c[2]), "+f"(c[3])
        : "r"(a[0]), "r"(a[1]), "r"(a[2]), "r"(a[3]), "r"(b0), "r"(b1));
}

// packed key: bits(v + 4.0) masked, low 9 bits = 511-k  (v in [-2,2] => v+4>0,
// positive-float bits are monotonic; ties resolve to smaller k)
__device__ __forceinline__ uint32_t mkkey(float v, uint32_t idx) {
    return (__float_as_uint(v + 4.0f) & KEYMASK) | idx;
}

// branchless top-3 insert over packed keys (descending), 5 IMNMX
__device__ __forceinline__ void ins3k(uint32_t x, uint32_t* t) {
    uint32_t a = min(x, t[0]); t[0] = max(x, t[0]);
    uint32_t b = min(a, t[1]); t[1] = max(a, t[1]);
    t[2] = max(b, t[2]);
}

// EXACT scorer — replicates round-1 arithmetic (verified rel_err 0.0)
__device__ __forceinline__ float exact_d2(const float4* zr, float z2,
                                          const float* __restrict__ crow) {
    const float4* c4 = (const float4*)crow;
    float4 cv[16];
    #pragma unroll
    for (int i = 0; i < 16; i++) cv[i] = c4[i];
    float c2 = 0.f;
    #pragma unroll
    for (int i = 0; i < 16; i++) {
        c2 += cv[i].x * cv[i].x; c2 += cv[i].y * cv[i].y;
        c2 += cv[i].z * cv[i].z; c2 += cv[i].w * cv[i].w;
    }
    float a0 = 0.f, a1 = 0.f, a2 = 0.f, a3 = 0.f;
    #pragma unroll
    for (int i = 0; i < 16; i++) {
        a0 += zr[i].x * cv[i].x;
        a1 += zr[i].y * cv[i].y;
        a2 += zr[i].z * cv[i].z;
        a3 += zr[i].w * cv[i].w;
    }
    float dot = (a0 + a1) + (a2 + a3);
    return (z2 - 2.0f * dot) + c2;
}

__device__ __forceinline__ float z2_of(const float4* zr) {
    float z2 = 0.f;
    #pragma unroll
    for (int i = 0; i < 16; i++)
        z2 += zr[i].x * zr[i].x + zr[i].y * zr[i].y
            + zr[i].z * zr[i].z + zr[i].w * zr[i].w;
    return z2;
}

__device__ __forceinline__ uint32_t packh2(float x, float y) {
    __nv_half2_raw h2 = __halves2half2(__float2half_rn(x), __float2half_rn(y));
    return *(uint32_t*)&h2;
}

// A row: convert 64 f32 -> fp16, row-major words, return sum of squares
__device__ __forceinline__ float stage_row_fp16(char* dst, const float4* v) {
    float s = 0.f;
    #pragma unroll
    for (int i = 0; i < 16; i++) {
        float4 a = v[i];
        s += a.x * a.x + a.y * a.y + a.z * a.z + a.w * a.w;
        uint2 w;
        w.x = packh2(a.x, a.y);
        w.y = packh2(a.z, a.w);
        *(uint2*)(dst + i * 8) = w;
    }
    return s;
}

// B row: convert + store PERMUTED: thread (qr,qc) reads its 8 fragment words
// contiguously at byte offset qc*32.
__device__ __forceinline__ float stage_row_b_perm(char* dst, const float4* v) {
    float s = 0.f;
    uint32_t w[32];
    #pragma unroll
    for (int i = 0; i < 16; i++) {
        float4 a = v[i];
        s += a.x * a.x + a.y * a.y + a.z * a.z + a.w * a.w;
        w[2 * i]     = packh2(a.x, a.y);
        w[2 * i + 1] = packh2(a.z, a.w);
    }
    *(uint4*)(dst +   0) = make_uint4(w[0],  w[4],  w[8],  w[12]);
    *(uint4*)(dst +  16) = make_uint4(w[16], w[20], w[24], w[28]);
    *(uint4*)(dst +  32) = make_uint4(w[1],  w[5],  w[9],  w[13]);
    *(uint4*)(dst +  48) = make_uint4(w[17], w[21], w[25], w[29]);
    *(uint4*)(dst +  64) = make_uint4(w[2],  w[6],  w[10], w[14]);
    *(uint4*)(dst +  80) = make_uint4(w[18], w[22], w[26], w[30]);
    *(uint4*)(dst +  96) = make_uint4(w[3],  w[7],  w[11], w[15]);
    *(uint4*)(dst + 112) = make_uint4(w[19], w[23], w[27], w[31]);
    return s;
}

// ============================================================================
// Main kernel: persistent, 2 CTAs/SM, 8 warps, M-tile 128 (1 m16 strip/warp)
// ============================================================================
__global__ __launch_bounds__(TPB, 2)
void vq_mma(const float* __restrict__ z, const float* __restrict__ cb,
            int N, float* __restrict__ q_out, float* __restrict__ ids_out,
            float* __restrict__ loss_out)
{
    extern __shared__ char smem[];
    const int tid  = threadIdx.x;
    const int wid  = tid >> 5;
    const int lane = tid & 31;
    const int qr   = lane >> 2;   // 0..7
    const int qc   = lane & 3;    // 0..3

    float* c2h  = (float*)(smem + C2H_OFF);
    float* c2n  = (float*)(smem + C2N_OFF);
    float* z2s  = (float*)(smem + Z2S_OFF);
    int*   kidS = (int*)(smem + KID_OFF);
    float* cnp  = (float*)(smem + CN_OFF);

    // ---- stage codebook once: permuted fp16 rows + +-0.5*||c||^2 ----
    for (int n = tid; n < KCODES; n += TPB) {
        float4 cv[16];
        const float4* c4 = (const float4*)(cb + (size_t)n * D);
        #pragma unroll
        for (int i = 0; i < 16; i++) cv[i] = c4[i];
        float s = stage_row_b_perm(smem + B_OFF + n * 144, cv);
        c2h[n] =  0.5f * s;
        c2n[n] = -0.5f * s;
    }
    __syncthreads();
    if (tid < 32) {
        float m = 0.f;
        for (int i = tid; i < KCODES; i += 32) m = fmaxf(m, c2h[i]);
        #pragma unroll
        for (int off = 16; off; off >>= 1)
            m = fmaxf(m, __shfl_xor_sync(0xffffffffu, m, off));
        if (tid == 0) *cnp = sqrtf(2.0f * m);
    }
    __syncthreads();
    const float CNMAX = *cnp;

    const int ntiles = N / MTILE;
    double dsum = 0.0;

    for (int tile = blockIdx.x; tile < ntiles; tile += gridDim.x) {
        // ---- stage A tile: threads 0..127 convert one row each ----
        if (tid < MTILE) {
            float4 zr[16];
            const float4* zp = (const float4*)(z + (size_t)(tile * MTILE + tid) * D);
            #pragma unroll
            for (int i = 0; i < 16; i++) zr[i] = zp[i];
            z2s[tid] = stage_row_fp16(smem + A_OFF + tid * 144, zr);
        }
        __syncthreads();

        // ---- A fragments (hoisted; strip rows wid*16+qr, +8) ----
        uint32_t afr[4][4];
        {
            const int r0b = (wid * 16 + qr) * 144;
            #pragma unroll
            for (int ks = 0; ks < 4; ks++) {
                const int kb = ks * 32 + qc * 4;
                afr[ks][0] = *(const uint32_t*)(smem + A_OFF + r0b + kb);
                afr[ks][1] = *(const uint32_t*)(smem + A_OFF + r0b + 8 * 144 + kb);
                afr[ks][2] = *(const uint32_t*)(smem + A_OFF + r0b + kb + 16);
                afr[ks][3] = *(const uint32_t*)(smem + A_OFF + r0b + 8 * 144 + kb + 16);
            }
        }

        // ---- MMA + per-thread packed-key top-3 for 2 row-slots ----
        uint32_t tkey[2][3];
        #pragma unroll
        for (int s = 0; s < 2; s++)
            tkey[s][0] = tkey[s][1] = tkey[s][2] = 0u;

        for (int grp = 0; grp < 16; grp++) {   // 16 groups of 32 codes
            float acc[4][4];
            uint4 ra[4], rb[4];
            #pragma unroll
            for (int c = 0; c < 4; c++) {
                const int col0 = grp * 32 + c * 8 + qc * 2;
                const float2 nh = *(const float2*)&c2n[col0];
                acc[c][0] = nh.x; acc[c][1] = nh.y;   // init = -0.5*||c||^2
                acc[c][2] = nh.x; acc[c][3] = nh.y;
                const char* bp = smem + B_OFF
                               + (grp * 32 + c * 8 + qr) * 144 + qc * 32;
                ra[c] = *(const uint4*)(bp);
                rb[c] = *(const uint4*)(bp + 16);
            }
            #pragma unroll
            for (int c = 0; c < 4; c++) mma_fp16(acc[c], afr[0], ra[c].x, ra[c].y);
            #pragma unroll
            for (int c = 0; c < 4; c++) mma_fp16(acc[c], afr[1], ra[c].z, ra[c].w);
            #pragma unroll
            for (int c = 0; c < 4; c++) mma_fp16(acc[c], afr[2], rb[c].x, rb[c].y);
            #pragma unroll
            for (int c = 0; c < 4; c++) mma_fp16(acc[c], afr[3], rb[c].z, rb[c].w);

            #pragma unroll
            for (int c = 0; c < 4; c++) {
                const int col0 = grp * 32 + c * 8 + qc * 2;
                const uint32_t i0 = 511 - col0;
                ins3k(mkkey(acc[c][0], i0),     tkey[0]);
                ins3k(mkkey(acc[c][1], i0 - 1), tkey[0]);
                ins3k(mkkey(acc[c][2], i0),     tkey[1]);
                ins3k(mkkey(acc[c][3], i0 - 1), tkey[1]);
            }
        }

        const uint32_t loc3_0 = tkey[0][2];
        const uint32_t loc3_1 = tkey[1][2];

        // ---- quad merge (xor 1, 2) -> global top-3 per slot ----
        #pragma unroll
        for (int off = 1; off <= 2; off <<= 1) {
            #pragma unroll
            for (int s = 0; s < 2; s++) {
                uint32_t k0 = tkey[s][0], k1 = tkey[s][1], k2 = tkey[s][2];
                uint32_t o0 = __shfl_xor_sync(0xffffffffu, k0, off);
                uint32_t o1 = __shfl_xor_sync(0xffffffffu, k1, off);
                uint32_t o2 = __shfl_xor_sync(0xffffffffu, k2, off);
                ins3k(o0, tkey[s]);
                ins3k(o1, tkey[s]);
                ins3k(o2, tkey[s]);
            }
        }

        // ---- per-row rigorous threshold (fp16 2^-9 bound + key-quant slack) ----
        const int r0 = wid * 16 + qr;
        const float thr0 = sqrtf(z2s[r0])     * CNMAX * 0.001953125f + 1.2e-3f;
        const float thr1 = sqrtf(z2s[r0 + 8]) * CNMAX * 0.001953125f + 1.2e-3f;

        // cutkey: biased top value minus thr, masked (conservative down-round)
        const float b1b0 = __uint_as_float(tkey[0][0] & KEYMASK);
        const float b1b1 = __uint_as_float(tkey[1][0] & KEYMASK);
        const uint32_t cut0 = __float_as_uint(b1b0 - thr0) & KEYMASK;
        const uint32_t cut1 = __float_as_uint(b1b1 - thr1) & KEYMASK;

        unsigned bal0 = __ballot_sync(0xffffffffu, loc3_0 >= cut0);
        unsigned bal1 = __ballot_sync(0xffffffffu, loc3_1 >= cut1);
        const unsigned qsh = lane & ~3;
        const bool u0 = ((bal0 >> qsh) & 0xFu) != 0;
        const bool u1 = ((bal1 >> qsh) & 0xFu) != 0;

        // ---- finalize: lane qc=0 -> slot 0, qc=1 -> slot 1 ----
        const bool mine = (qc < 2);
        const int  myrow = r0 + qc * 8;                 // valid when mine
        const bool my_unsafe = mine && (qc == 0 ? u0 : u1);
        int kid = 0;

        if (mine && !my_unsafe) {
            const int s = qc;
            const uint32_t K0 = tkey[s][0], K1 = tkey[s][1], K2 = tkey[s][2];
            const uint32_t cut = (s == 0) ? cut0 : cut1;
            int ck[3]; int nc = 1;
            ck[0] = 511 - (int)(K0 & 0x1FFu);
            if (K1 >= cut) ck[nc++] = 511 - (int)(K1 & 0x1FFu);
            if (K2 >= cut) ck[nc++] = 511 - (int)(K2 & 0x1FFu);
            if (nc == 1) {
                kid = ck[0];                            // margin proves winner
            } else {
                if (ck[0] > ck[1]) { int t = ck[0]; ck[0] = ck[1]; ck[1] = t; }
                if (nc == 3) {
                    if (ck[1] > ck[2]) { int t = ck[1]; ck[1] = ck[2]; ck[2] = t; }
                    if (ck[0] > ck[1]) { int t = ck[0]; ck[0] = ck[1]; ck[1] = t; }
                }
                const int grow = tile * MTILE + myrow;
                float4 zr[16];
                const float4* zp = (const float4*)(z + (size_t)grow * D);
                #pragma unroll
                for (int i = 0; i < 16; i++) zr[i] = zp[i];
                const float z2 = z2_of(zr);
                float best = 3.402823466e38f; kid = ck[0];
                for (int i = 0; i < nc; i++) {          // ascending k, strict <
                    float d = exact_d2(zr, z2, cb + (size_t)ck[i] * D);
                    if (d < best) { best = d; kid = ck[i]; }
                }
            }
        }

        // ---- warp-cooperative exact scan for unsafe rows (rare) ----
        unsigned need = __ballot_sync(0xffffffffu, my_unsafe);
        while (need) {
            const int src = __ffs(need) - 1;
            need &= need - 1;
            const int rl = __shfl_sync(0xffffffffu, myrow, src);
            const int grow = tile * MTILE + rl;
            float4 zr[16];
            const float4* zp = (const float4*)(z + (size_t)grow * D);
            #pragma unroll
            for (int i = 0; i < 16; i++) zr[i] = zp[i];
            const float z2 = z2_of(zr);
            float best = 3.402823466e38f; int bk = KCODES;
            for (int k = lane; k < KCODES; k += 32) {   // lane-ascending, strict <
                float d = exact_d2(zr, z2, cb + (size_t)k * D);
                if (d < best) { best = d; bk = k; }
            }
            #pragma unroll
            for (int off = 16; off; off >>= 1) {
                float ob = __shfl_xor_sync(0xffffffffu, best, off);
                int   obk = __shfl_xor_sync(0xffffffffu, bk, off);
                if (ob < best || (ob == best && obk < bk)) { best = ob; bk = obk; }
            }
            if (lane == src) kid = bk;
        }

        if (mine) kidS[myrow] = kid;
        __syncthreads();

        // ---- epilogue: threads 0..127, row tid (no end-of-loop sync needed:
        //  epilogue reads kidS/global only; staging writes A/z2s only) ----
        if (tid < MTILE) {
            const int grow = tile * MTILE + tid;
            const int k = kidS[tid];
            float4 zr[16];
            const float4* zp = (const float4*)(z + (size_t)grow * D);
            #pragma unroll
            for (int i = 0; i < 16; i++) zr[i] = zp[i];
            const float4* q4 = (const float4*)(cb + (size_t)k * D);
            float4* qo = (float4*)(q_out + (size_t)grow * D);
            float lsum = 0.f;
            #pragma unroll
            for (int i = 0; i < 16; i++) {
                float4 cv = q4[i];
                float4 zv = zr[i];
                float dx = zv.x - cv.x, dy = zv.y - cv.y;
                float dz = zv.z - cv.z, dw = zv.w - cv.w;
                lsum += dx * dx + dy * dy + dz * dz + dw * dw;
                float4 o;
                o.x = zv.x + (cv.x - zv.x);   // fl(z + fl(q - z)), reference STE
                o.y = zv.y + (cv.y - zv.y);
                o.z = zv.z + (cv.z - zv.z);
                o.w = zv.w + (cv.w - zv.w);
                qo[i] = o;
            }
            if (ids_out) ids_out[grow] = (float)k;
            dsum += (double)lsum;
        }
    }

    // ---- deterministic per-CTA loss reduction ----
    __syncthreads();
    double* red = (double*)(smem + B_OFF);   // codebook region reusable now
    red[tid] = dsum;
    __syncthreads();
    if (tid == 0) {
        double s = 0.0;
        for (int i = 0; i < TPB; i++) s += red[i];
        g_partial[blockIdx.x] = s;
    }

    // ---- fused finalize: last CTA computes the loss (deterministic order) ----
    if (loss_out) {
        __shared__ unsigned s_last;
        if (tid == 0) {
            __threadfence();
            unsigned p = atomicAdd(&g_count, 1u);
            s_last = (p == gridDim.x - 1) ? 1u : 0u;
        }
        __syncthreads();
        if (s_last) {
            __threadfence();
            double s = 0.0;
            for (int i = tid; i < (int)gridDim.x; i += TPB) s += g_partial[i];
            double* sp = (double*)(smem + B_OFF);
            sp[tid] = s;
            __syncthreads();
            for (int off = TPB / 2; off; off >>= 1) {
                if (tid < off) sp[tid] += sp[tid + off];
                __syncthreads();
            }
            if (tid == 0) {
                double mean = sp[0] / ((double)N * (double)D);
                loss_out[0] = (float)(mean + 0.25 * mean);
                g_count = 0;                 // reset for graph replay
            }
        }
    }
}

// ============================================================================
// Generic fallback (round-2 kernel) for unexpected shapes
// ============================================================================
#define FTPB 256
#define ROW_PAD 68
__global__ __launch_bounds__(FTPB) void vq_ref(
    const float* __restrict__ z, const float* __restrict__ cb,
    int N, int K, float* __restrict__ q_out, float* __restrict__ ids_out)
{
    extern __shared__ float fsm[];
    float* cbs = fsm;
    float* c2  = fsm + (size_t)K * ROW_PAD;
    const int tid = threadIdx.x;
    const float4* cb4 = (const float4*)cb;
    const int nvec = K * (D / 4);
    for (int idx = tid; idx < nvec; idx += FTPB) {
        int k = idx >> 4, c = idx & 15;
        *(float4*)&cbs[k * ROW_PAD + c * 4] = cb4[idx];
    }
    __syncthreads();
    for (int k = tid; k < K; k += FTPB) {
        const float* r = &cbs[k * ROW_PAD];
        float s = 0.f;
        #pragma unroll
        for (int i = 0; i < D; i++) s += r[i] * r[i];
        c2[k] = s;
    }
    __syncthreads();
    const int row = blockIdx.x * FTPB + tid;
    float lsum = 0.f;
    if (row < N) {
        float4 zr[16];
        const float4* zp = (const float4*)(z + (size_t)row * D);
        #pragma unroll
        for (int i = 0; i < 16; i++) zr[i] = zp[i];
        float z2 = 0.f;
        #pragma unroll
        for (int i = 0; i < 16; i++)
            z2 += zr[i].x * zr[i].x + zr[i].y * zr[i].y
                + zr[i].z * zr[i].z + zr[i].w * zr[i].w;
        float best = 3.402823466e38f; int bid = 0;
        for (int k = 0; k < K; k++) {
            const float4* crow = (const float4*)&cbs[k * ROW_PAD];
            float a0 = 0.f, a1 = 0.f, a2 = 0.f, a3 = 0.f;
            #pragma unroll
            for (int i = 0; i < 16; i++) {
                float4 cv = crow[i];
                a0 += zr[i].x * cv.x; a1 += zr[i].y * cv.y;
                a2 += zr[i].z * cv.z; a3 += zr[i].w * cv.w;
            }
            float dot = (a0 + a1) + (a2 + a3);
            float d = (z2 - 2.0f * dot) + c2[k];
            if (d < best) { best = d; bid = k; }
        }
        const float4* crow = (const float4*)&cbs[bid * ROW_PAD];
        float4* qo = (float4*)(q_out + (size_t)row * D);
        #pragma unroll
        for (int i = 0; i < 16; i++) {
            float4 cv = crow[i];
            float4 zv = zr[i];
            float dx = zv.x - cv.x, dy = zv.y - cv.y;
            float dz = zv.z - cv.z, dw = zv.w - cv.w;
            lsum += dx * dx + dy * dy + dz * dz + dw * dw;
            float4 o;
            o.x = zv.x + (cv.x - zv.x); o.y = zv.y + (cv.y - zv.y);
            o.z = zv.z + (cv.z - zv.z); o.w = zv.w + (cv.w - zv.w);
            qo[i] = o;
        }
        if (ids_out) ids_out[row] = (float)bid;
    }
    #pragma unroll
    for (int off = 16; off; off >>= 1)
        lsum += __shfl_down_sync(0xffffffffu, lsum, off);
    __shared__ double wp[FTPB / 32];
    if ((tid & 31) == 0) wp[tid >> 5] = (double)lsum;
    __syncthreads();
    if (tid == 0) {
        double s = 0.0;
        #pragma unroll
        for (int w = 0; w < FTPB / 32; w++) s += wp[w];
        g_partial[blockIdx.x] = s;
    }
}

__global__ void vq_finalize(int nblocks, double inv_total, float* loss_out)
{
    __shared__ double sp[256];
    const int tid = threadIdx.x;
    double s = 0.0;
    for (int i = tid; i < nblocks; i += 256) s += g_partial[i];
    sp[tid] = s;
    __syncthreads();
    for (int off = 128; off; off >>= 1) {
        if (tid < off) sp[tid] += sp[tid + off];
        __syncthreads();
    }
    if (tid == 0) {
        double mean = sp[0] * inv_total;
        loss_out[0] = (float)(mean + 0.25 * mean);
    }
}

extern "C" void kernel_launch(void* const* d_in, const int* in_sizes, int n_in,
                              void* d_out, int out_size)
{
    const float* z  = (const float*)d_in[0];
    const float* cb = (const float*)d_in[1];
    const int N = in_sizes[0] / D;
    const int K = in_sizes[1] / D;

    float* out = (float*)d_out;
    float* q_out    = out;
    float* loss_ptr = nullptr;
    float* ids_ptr  = nullptr;
    const long base = (long)N * D;
    if ((long)out_size >= base + 1 + N) { loss_ptr = out + base; ids_ptr = out + base + 1; }
    else if ((long)out_size == base + N) { ids_ptr = out + base; }
    else if ((long)out_size == base + 1) { loss_ptr = out + base; }

    if (K == KCODES && (N % MTILE) == 0 && N > 0) {
        const int ntiles = N / MTILE;
        const int nblocks = ntiles < GRID_MAX ? ntiles : GRID_MAX;
        cudaFuncSetAttribute(vq_mma, cudaFuncAttributeMaxDynamicSharedMemorySize, SMEM_TOTAL);
        vq_mma<<<nblocks, TPB, SMEM_TOTAL>>>(z, cb, N, q_out, ids_ptr, loss_ptr);
    } else {
        const size_t smem_bytes = ((size_t)K * ROW_PAD + K) * sizeof(float);
        cudaFuncSetAttribute(vq_ref, cudaFuncAttributeMaxDynamicSharedMemorySize, (int)smem_bytes);
        const int nblocks = (N + FTPB - 1) / FTPB;
        vq_ref<<<nblocks, FTPB, smem_bytes>>>(z, cb, N, K, q_out, ids_ptr);
        if (loss_ptr) {
            double inv_total = 1.0 / ((double)N * (double)D);
            vq_finalize<<<1, 256>>>(nblocks, inv_total, loss_ptr);
        }
    }
}